// round 7
// baseline (speedup 1.0000x reference)
#include <cuda_runtime.h>
#include <cuda_bf16.h>
#include <math.h>
#include <stdint.h>

#define D   256
#define NA  16
#define NC  256

// ---------------------------------------------------------------------------
// Scratch (device globals — no allocation allowed in kernel_launch)
// ---------------------------------------------------------------------------
__device__ float g_qads[8192u  * 256u];
__device__ float g_kads[8192u  * 256u];
__device__ float g_vads[8192u  * 256u];
__device__ float g_qcat[131072u * 256u];
__device__ float g_kcat[131072u * 256u];
__device__ float g_vcat[131072u * 256u];
__device__ __nv_bfloat16 gx_ads_hi[8192u  * 256u];
__device__ __nv_bfloat16 gx_ads_lo[8192u  * 256u];
__device__ __nv_bfloat16 gx_cat_hi[131072u * 256u];
__device__ __nv_bfloat16 gx_cat_lo[131072u * 256u];
__device__ __nv_bfloat16 gw_hi[6u * 65536u];
__device__ __nv_bfloat16 gw_lo[6u * 65536u];

// ---------------------------------------------------------------------------
// PTX helpers (arch-neutral sm_80+ — harness ptxas target is plain sm_103)
// ---------------------------------------------------------------------------
__device__ __forceinline__ uint32_t smem_u32(const void* p) {
    uint32_t a;
    asm("{ .reg .u64 t; cvta.to.shared.u64 t, %1; cvt.u32.u64 %0, t; }"
        : "=r"(a) : "l"(p));
    return a;
}
__device__ __forceinline__ void cpa16(uint32_t dst, const void* src) {
    asm volatile("cp.async.ca.shared.global [%0], [%1], 16;"
                 :: "r"(dst), "l"(src) : "memory");
}
__device__ __forceinline__ void ldm_x4(uint32_t* r, uint32_t addr) {
    asm volatile("ldmatrix.sync.aligned.m8n8.x4.shared.b16 {%0,%1,%2,%3}, [%4];"
                 : "=r"(r[0]), "=r"(r[1]), "=r"(r[2]), "=r"(r[3]) : "r"(addr));
}
__device__ __forceinline__ void mma16816(float* c, const uint32_t* a,
                                         const uint32_t* b) {
    asm volatile(
        "mma.sync.aligned.m16n8k16.row.col.f32.bf16.bf16.f32 "
        "{%0,%1,%2,%3}, {%4,%5,%6,%7}, {%8,%9}, {%0,%1,%2,%3};"
        : "+f"(c[0]), "+f"(c[1]), "+f"(c[2]), "+f"(c[3])
        : "r"(a[0]), "r"(a[1]), "r"(a[2]), "r"(a[3]), "r"(b[0]), "r"(b[1]));
}
__device__ __forceinline__ void split2(float a, float b, uint32_t& hp, uint32_t& lp) {
    asm("cvt.rn.bf16x2.f32 %0, %1, %2;" : "=r"(hp) : "f"(b), "f"(a));
    float af = __uint_as_float(hp << 16);
    float bf = __uint_as_float(hp & 0xFFFF0000u);
    float la = a - af, lb = b - bf;
    asm("cvt.rn.bf16x2.f32 %0, %1, %2;" : "=r"(lp) : "f"(lb), "f"(la));
}

// ---------------------------------------------------------------------------
// Conversion prepass: fp32 -> packed bf16 hi/lo
// ---------------------------------------------------------------------------
__global__ void __launch_bounds__(256)
conv_x(const float4* __restrict__ src, uint2* __restrict__ hi,
       uint2* __restrict__ lo, int n4)
{
    for (int i = blockIdx.x * blockDim.x + threadIdx.x; i < n4;
         i += gridDim.x * blockDim.x) {
        float4 f = src[i];
        uint32_t h0, h1, l0, l1;
        split2(f.x, f.y, h0, l0);
        split2(f.z, f.w, h1, l1);
        hi[i] = make_uint2(h0, h1);
        lo[i] = make_uint2(l0, l1);
    }
}

__global__ void __launch_bounds__(256)
conv_w(const float* w0, const float* w1, const float* w2,
       const float* w3, const float* w4, const float* w5,
       uint2* __restrict__ hi, uint2* __restrict__ lo)
{
    const int z = blockIdx.y;
    const float* W = (z == 0) ? w0 : (z == 1) ? w1 : (z == 2) ? w2
                   : (z == 3) ? w3 : (z == 4) ? w4 : w5;
    const int i = blockIdx.x * 256 + threadIdx.x;   // 0..16383
    float4 f = ((const float4*)W)[i];
    uint32_t h0, h1, l0, l1;
    split2(f.x, f.y, h0, l0);
    split2(f.z, f.w, h1, l1);
    hi[z * 16384 + i] = make_uint2(h0, h1);
    lo[z * 16384 + i] = make_uint2(l0, l1);
}

// ---------------------------------------------------------------------------
// Pipelined bf16 GEMM: Y[M,256] = X @ W^T + bias (W z-fused: q/k/v)
// 256 thr / 8 warps (4m x 2n of 32x64), CTA tile 128x128, BK=32,
// 3-stage cp.async pipeline, XOR-swizzled smem (no pad), 1 sync/chunk.
// Stage = 4 matrices (Ahi|Alo|Bhi|Blo) x 128 rows x 64 B = 32,768 B.
// ---------------------------------------------------------------------------
#define SROW   64u
#define SMAT   8192u
#define SSTAGE 32768u

// swizzled byte offset of (row, 16B-chunk) within one matrix
__device__ __forceinline__ uint32_t swz(uint32_t row, uint32_t chunk) {
    return row * 64u + (((chunk ^ (row >> 1)) & 3u) << 4);
}

__global__ void __launch_bounds__(256, 2)
gemm_pipe(const __nv_bfloat16* __restrict__ Xhi, const __nv_bfloat16* __restrict__ Xlo,
          const __nv_bfloat16* __restrict__ Wh_all, const __nv_bfloat16* __restrict__ Wl_all,
          const float* __restrict__ b0, const float* __restrict__ b1,
          const float* __restrict__ b2,
          float* __restrict__ Y0, float* __restrict__ Y1, float* __restrict__ Y2)
{
    const int z = blockIdx.z;
    const __nv_bfloat16* Whi = Wh_all + (size_t)z * 65536;
    const __nv_bfloat16* Wlo = Wl_all + (size_t)z * 65536;
    const float* bias = (z == 0) ? b0 : (z == 1) ? b1 : b2;
    float*       Y    = (z == 0) ? Y0 : (z == 1) ? Y1 : Y2;

    extern __shared__ __align__(16) char smraw[];
    const uint32_t sb = smem_u32(smraw);

    const int tid  = threadIdx.x;
    const int lane = tid & 31;
    const int wid  = tid >> 5;
    const int wm   = wid & 3;
    const int wn   = wid >> 2;
    const int m0   = blockIdx.x * 128;
    const int n0   = blockIdx.y * 128;

    float acc[2][8][4];
#pragma unroll
    for (int i = 0; i < 2; i++)
#pragma unroll
        for (int j = 0; j < 8; j++)
#pragma unroll
            for (int t = 0; t < 4; t++) acc[i][j][t] = 0.f;

    // copy coords: 512 16B copies per matrix, 2 per thread
    const int c0r = tid >> 2,        c0c = tid & 3;
    const int c1r = c0r + 64,        c1c = c0c;
    const uint32_t d0 = swz((uint32_t)c0r, (uint32_t)c0c);
    const uint32_t d1 = swz((uint32_t)c1r, (uint32_t)c1c);

#define ISSUE(stage, kk)                                                          \
    do {                                                                          \
        const uint32_t s = sb + (stage) * SSTAGE;                                 \
        const char* xh = (const char*)(Xhi + (size_t)(m0 + c0r) * 256 + (kk));    \
        const char* xl = (const char*)(Xlo + (size_t)(m0 + c0r) * 256 + (kk));    \
        const char* wh = (const char*)(Whi + (size_t)(n0 + c0r) * 256 + (kk));    \
        const char* wl = (const char*)(Wlo + (size_t)(n0 + c0r) * 256 + (kk));    \
        cpa16(s + 0*SMAT + d0, xh + c0c * 16);                                    \
        cpa16(s + 1*SMAT + d0, xl + c0c * 16);                                    \
        cpa16(s + 2*SMAT + d0, wh + c0c * 16);                                    \
        cpa16(s + 3*SMAT + d0, wl + c0c * 16);                                    \
        const char* xh2 = (const char*)(Xhi + (size_t)(m0 + c1r) * 256 + (kk));   \
        const char* xl2 = (const char*)(Xlo + (size_t)(m0 + c1r) * 256 + (kk));   \
        const char* wh2 = (const char*)(Whi + (size_t)(n0 + c1r) * 256 + (kk));   \
        const char* wl2 = (const char*)(Wlo + (size_t)(n0 + c1r) * 256 + (kk));   \
        cpa16(s + 0*SMAT + d1, xh2 + c1c * 16);                                   \
        cpa16(s + 1*SMAT + d1, xl2 + c1c * 16);                                   \
        cpa16(s + 2*SMAT + d1, wh2 + c1c * 16);                                   \
        cpa16(s + 3*SMAT + d1, wl2 + c1c * 16);                                   \
        asm volatile("cp.async.commit_group;" ::: "memory");                      \
    } while (0)

    // per-lane ldmatrix row bases (row fixed per lane & matrix; chunk varies)
    const int l15 = lane & 15, lhi = lane >> 4;
    uint32_t arow[2], axor[2], brow[4], bxor[4];
#pragma unroll
    for (int i = 0; i < 2; i++) {
        uint32_t r = (uint32_t)(wm * 32 + i * 16 + l15);
        arow[i] = r * 64u;
        axor[i] = (r >> 1) & 3u;
    }
#pragma unroll
    for (int bp = 0; bp < 4; bp++) {
        uint32_t r = (uint32_t)(wn * 64 + bp * 16 + l15);
        brow[bp] = r * 64u;
        bxor[bp] = (r >> 1) & 3u;
    }

    ISSUE(0, 0);
    ISSUE(1, 32);

#pragma unroll 1
    for (int c = 0; c < 8; c++) {
        if (c < 7)
            asm volatile("cp.async.wait_group 1;" ::: "memory");
        else
            asm volatile("cp.async.wait_group 0;" ::: "memory");
        __syncthreads();

        const uint32_t st = sb + (uint32_t)(c % 3) * SSTAGE;
#pragma unroll
        for (int ks = 0; ks < 2; ks++) {
            const uint32_t cb = (uint32_t)(ks * 2 + lhi);   // chunk idx 0..3
            uint32_t ah[2][4], al[2][4], b[8][2], bl[8][2], r[4];

            // A hi + B hi
#pragma unroll
            for (int i = 0; i < 2; i++)
                ldm_x4(ah[i], st + 0*SMAT + arow[i] + (((cb ^ axor[i]) & 3u) << 4));
#pragma unroll
            for (int bp = 0; bp < 4; bp++) {
                ldm_x4(r, st + 2*SMAT + brow[bp] + (((cb ^ bxor[bp]) & 3u) << 4));
                b[2*bp][0] = r[0]; b[2*bp+1][0] = r[1];
                b[2*bp][1] = r[2]; b[2*bp+1][1] = r[3];
            }
            // prefetch A lo before hi*hi MMAs
#pragma unroll
            for (int i = 0; i < 2; i++)
                ldm_x4(al[i], st + 1*SMAT + arow[i] + (((cb ^ axor[i]) & 3u) << 4));
#pragma unroll
            for (int am = 0; am < 2; am++)
#pragma unroll
                for (int bn = 0; bn < 8; bn++) mma16816(acc[am][bn], ah[am], b[bn]);

            // prefetch B lo before lo*hi MMAs
#pragma unroll
            for (int bp = 0; bp < 4; bp++) {
                ldm_x4(r, st + 3*SMAT + brow[bp] + (((cb ^ bxor[bp]) & 3u) << 4));
                bl[2*bp][0] = r[0]; bl[2*bp+1][0] = r[1];
                bl[2*bp][1] = r[2]; bl[2*bp+1][1] = r[3];
            }
#pragma unroll
            for (int am = 0; am < 2; am++)
#pragma unroll
                for (int bn = 0; bn < 8; bn++) mma16816(acc[am][bn], al[am], b[bn]);
#pragma unroll
            for (int am = 0; am < 2; am++)
#pragma unroll
                for (int bn = 0; bn < 8; bn++) mma16816(acc[am][bn], ah[am], bl[bn]);
        }

        if (c + 2 < 8) ISSUE((c + 2) % 3, (c + 2) * 32);
    }

    const int orow  = m0 + wm * 32 + (lane >> 2);
    const int ocol0 = n0 + wn * 64 + (lane & 3) * 2;
#pragma unroll
    for (int am = 0; am < 2; am++) {
#pragma unroll
        for (int bn = 0; bn < 8; bn++) {
            const int col = ocol0 + bn * 8;
            float2 bv = *(const float2*)(bias + col);
            float2 v0, v1;
            v0.x = acc[am][bn][0] + bv.x; v0.y = acc[am][bn][1] + bv.y;
            v1.x = acc[am][bn][2] + bv.x; v1.y = acc[am][bn][3] + bv.y;
            *(float2*)(Y + (size_t)(orow + am * 16)     * 256 + col) = v0;
            *(float2*)(Y + (size_t)(orow + am * 16 + 8) * 256 + col) = v1;
        }
    }
}

// ---------------------------------------------------------------------------
// Fused attention (unchanged). blockIdx.x < B -> ads, else cat. 256 threads.
// ---------------------------------------------------------------------------
__device__ __forceinline__ float dot8(float4 a0, float4 b0, float4 a1, float4 b1) {
    return a0.x*b0.x + a0.y*b0.y + a0.z*b0.z + a0.w*b0.w
         + a1.x*b1.x + a1.y*b1.y + a1.z*b1.z + a1.w*b1.w;
}

__device__ void ads_part(float* sm, int b,
                         const float* __restrict__ q, const float* __restrict__ k,
                         const float* __restrict__ v, const float* __restrict__ h,
                         float* __restrict__ out)
{
    float* Qs = sm;
    float* Ps = sm + 16 * 260;
    const int tid = threadIdx.x;
    const float scale = 0.0625f;

    {
        const float4* src = (const float4*)(q + (size_t)b * (NA * D));
#pragma unroll
        for (int h2 = 0; h2 < 4; h2++) {
            int i = tid + h2 * 256;
            int row = i >> 6, col = (i & 63) << 2;
            float4 vv = src[i];
            float* d = Qs + row * 260 + col;
            d[0] = vv.x; d[1] = vv.y; d[2] = vv.z; d[3] = vv.w;
        }
    }
    __syncthreads();

    const int w = tid >> 5, l = tid & 31;

#pragma unroll 1
    for (int bat = 0; bat < 8; bat++) {
        const int c0 = w * 32 + bat * 4;
        float4 kA[4], kB[4];
#pragma unroll
        for (int kk = 0; kk < 4; kk++) {
            const float* kr = k + ((size_t)b * NC + c0 + kk) * D;
            kA[kk] = *(const float4*)(kr + 4 * l);
            kB[kk] = *(const float4*)(kr + 128 + 4 * l);
        }
        float s[64];
#pragma unroll
        for (int i = 0; i < 64; i++) s[i] = 0.f;
#pragma unroll
        for (int j = 0; j < 16; j++) {
            float4 qA = *(const float4*)(Qs + j * 260 + 4 * l);
            float4 qB = *(const float4*)(Qs + j * 260 + 128 + 4 * l);
#pragma unroll
            for (int kk = 0; kk < 4; kk++)
                s[kk * 16 + j] += dot8(qA, kA[kk], qB, kB[kk]);
        }
#pragma unroll
        for (int off = 16; off > 0; off >>= 1)
#pragma unroll
            for (int i = 0; i < 64; i++)
                s[i] += __shfl_xor_sync(0xffffffffu, s[i], off);
        if (l < 16) {
#pragma unroll
            for (int kk = 0; kk < 4; kk++)
                Ps[l * 260 + c0 + kk] = s[kk * 16 + l] * scale;
        }
    }
    __syncthreads();

    {
        for (int r = w; r < 16; r += 8) {
            float* row = Ps + r * 260;
            float vals[8];
            float mx = -1e30f;
#pragma unroll
            for (int j = 0; j < 8; j++) { vals[j] = row[l + 32*j]; mx = fmaxf(mx, vals[j]); }
#pragma unroll
            for (int o = 16; o > 0; o >>= 1) mx = fmaxf(mx, __shfl_xor_sync(0xffffffffu, mx, o));
            float sum = 0.f;
#pragma unroll
            for (int j = 0; j < 8; j++) { vals[j] = __expf(vals[j] - mx); sum += vals[j]; }
#pragma unroll
            for (int o = 16; o > 0; o >>= 1) sum += __shfl_xor_sync(0xffffffffu, sum, o);
            float inv = 1.f / sum;
#pragma unroll
            for (int j = 0; j < 8; j++) row[l + 32*j] = vals[j] * inv;
        }
    }
    __syncthreads();

    const int aq = tid >> 6;
    const int dg = tid & 63;
    float4 u[4];
#pragma unroll
    for (int qi = 0; qi < 4; qi++) u[qi] = make_float4(0,0,0,0);
    const float* vbase = v + (size_t)b * NC * D + dg * 4;
    const float* prow0 = Ps + (aq * 4) * 260;
#pragma unroll 4
    for (int c = 0; c < 256; c++) {
        float4 vv = *(const float4*)(vbase + (size_t)c * D);
#pragma unroll
        for (int qi = 0; qi < 4; qi++) {
            float p = prow0[qi * 260 + c];
            u[qi].x += p * vv.x; u[qi].y += p * vv.y;
            u[qi].z += p * vv.z; u[qi].w += p * vv.w;
        }
    }

    float ssq[4];
#pragma unroll
    for (int qi = 0; qi < 4; qi++) {
        const float4 hv = *(const float4*)(h + ((size_t)b * NA + aq * 4 + qi) * D + dg * 4);
        u[qi].x += hv.x; u[qi].y += hv.y; u[qi].z += hv.z; u[qi].w += hv.w;
        ssq[qi] = u[qi].x*u[qi].x + u[qi].y*u[qi].y + u[qi].z*u[qi].z + u[qi].w*u[qi].w;
    }
#pragma unroll
    for (int off = 16; off > 0; off >>= 1)
#pragma unroll
        for (int qi = 0; qi < 4; qi++)
            ssq[qi] += __shfl_xor_sync(0xffffffffu, ssq[qi], off);
    if (l == 0) {
#pragma unroll
        for (int qi = 0; qi < 4; qi++) Qs[w * 4 + qi] = ssq[qi];
    }
    __syncthreads();
#pragma unroll
    for (int qi = 0; qi < 4; qi++) {
        float tot = Qs[(2 * aq) * 4 + qi] + Qs[(2 * aq + 1) * 4 + qi];
        float inv = 1.f / fmaxf(sqrtf(tot), 1e-12f);
        float4 o;
        o.x = u[qi].x * inv; o.y = u[qi].y * inv;
        o.z = u[qi].z * inv; o.w = u[qi].w * inv;
        *(float4*)(out + ((size_t)b * NA + aq * 4 + qi) * D + dg * 4) = o;
    }
}

__device__ void cat_part(float* sm, int idx,
                         const float* __restrict__ q, const float* __restrict__ k,
                         const float* __restrict__ v, const float* __restrict__ h,
                         float* __restrict__ out)
{
    float* Ks = sm;
    float* Vs = sm + 16 * 260;
    const int tid = threadIdx.x;
    const int b = idx >> 3, xp = idx & 7;
    const float scale = 0.0625f;

    {
        const float4* ks = (const float4*)(k + (size_t)b * (NA * D));
        const float4* vs = (const float4*)(v + (size_t)b * (NA * D));
#pragma unroll
        for (int h2 = 0; h2 < 4; h2++) {
            int i = tid + h2 * 256;
            int row = i >> 6, col = (i & 63) << 2;
            float4 kv = ks[i];
            float* dk = Ks + row * 260 + col;
            dk[0] = kv.x; dk[1] = kv.y; dk[2] = kv.z; dk[3] = kv.w;
            float4 vv = vs[i];
            float* dv = Vs + row * 260 + col;
            dv[0] = vv.x; dv[1] = vv.y; dv[2] = vv.z; dv[3] = vv.w;
        }
    }
    __syncthreads();

    const int w = tid >> 5, l = tid & 31;
    const int c0 = xp * 32 + w * 4;
    const size_t gr0 = (size_t)b * NC + c0;

    float4 qA[4], qB[4];
#pragma unroll
    for (int qi = 0; qi < 4; qi++) {
        const float* qr = q + (gr0 + qi) * D;
        qA[qi] = *(const float4*)(qr + 4 * l);
        qB[qi] = *(const float4*)(qr + 128 + 4 * l);
    }

    float s[64];
#pragma unroll
    for (int i = 0; i < 64; i++) s[i] = 0.f;
#pragma unroll
    for (int j = 0; j < 16; j++) {
        float4 kA = *(const float4*)(Ks + j * 260 + 4 * l);
        float4 kB = *(const float4*)(Ks + j * 260 + 128 + 4 * l);
#pragma unroll
        for (int qi = 0; qi < 4; qi++)
            s[qi * 16 + j] += dot8(qA[qi], kA, qB[qi], kB);
    }
#pragma unroll
    for (int off = 16; off > 0; off >>= 1)
#pragma unroll
        for (int i = 0; i < 64; i++)
            s[i] += __shfl_xor_sync(0xffffffffu, s[i], off);

#pragma unroll
    for (int qi = 0; qi < 4; qi++) {
        float mx = -1e30f;
#pragma unroll
        for (int j = 0; j < 16; j++) mx = fmaxf(mx, s[qi * 16 + j]);
        float sum = 0.f;
#pragma unroll
        for (int j = 0; j < 16; j++) {
            float e = __expf((s[qi * 16 + j] - mx) * scale);
            s[qi * 16 + j] = e; sum += e;
        }
        float inv = 1.f / sum;
#pragma unroll
        for (int j = 0; j < 16; j++) s[qi * 16 + j] *= inv;
    }

    float4 uA[4], uB[4];
#pragma unroll
    for (int qi = 0; qi < 4; qi++) { uA[qi] = make_float4(0,0,0,0); uB[qi] = uA[qi]; }
#pragma unroll
    for (int j = 0; j < 16; j++) {
        float4 vA = *(const float4*)(Vs + j * 260 + 4 * l);
        float4 vB = *(const float4*)(Vs + j * 260 + 128 + 4 * l);
#pragma unroll
        for (int qi = 0; qi < 4; qi++) {
            float p = s[qi * 16 + j];
            uA[qi].x += p * vA.x; uA[qi].y += p * vA.y;
            uA[qi].z += p * vA.z; uA[qi].w += p * vA.w;
            uB[qi].x += p * vB.x; uB[qi].y += p * vB.y;
            uB[qi].z += p * vB.z; uB[qi].w += p * vB.w;
        }
    }

#pragma unroll
    for (int qi = 0; qi < 4; qi++) {
        const float* hr = h + (gr0 + qi) * D;
        float4 rA = *(const float4*)(hr + 4 * l);
        float4 rB = *(const float4*)(hr + 128 + 4 * l);
        rA.x += uA[qi].x; rA.y += uA[qi].y; rA.z += uA[qi].z; rA.w += uA[qi].w;
        rB.x += uB[qi].x; rB.y += uB[qi].y; rB.z += uB[qi].z; rB.w += uB[qi].w;
        float nn = rA.x*rA.x + rA.y*rA.y + rA.z*rA.z + rA.w*rA.w
                 + rB.x*rB.x + rB.y*rB.y + rB.z*rB.z + rB.w*rB.w;
#pragma unroll
        for (int o = 16; o > 0; o >>= 1) nn += __shfl_xor_sync(0xffffffffu, nn, o);
        float inv = 1.f / fmaxf(sqrtf(nn), 1e-12f);
        float* orow = out + (gr0 + qi) * D;
        *(float4*)(orow + 4 * l) =
            make_float4(rA.x*inv, rA.y*inv, rA.z*inv, rA.w*inv);
        *(float4*)(orow + 128 + 4 * l) =
            make_float4(rB.x*inv, rB.y*inv, rB.z*inv, rB.w*inv);
    }
}

__global__ void __launch_bounds__(256)
attn_fused(const float* qa, const float* kc, const float* vc, const float* hA,
           const float* qc, const float* ka, const float* va, const float* hC,
           float* outA, float* outC, int B)
{
    extern __shared__ __align__(16) float sm[];
    if ((int)blockIdx.x < B)
        ads_part(sm, blockIdx.x, qa, kc, vc, hA, outA);
    else
        cat_part(sm, blockIdx.x - B, qc, ka, va, hC, outC);
}

// ---------------------------------------------------------------------------
// Launch
// ---------------------------------------------------------------------------
extern "C" void kernel_launch(void* const* d_in, const int* in_sizes, int n_in,
                              void* d_out, int out_size)
{
    const float* h_ads = (const float*)d_in[0];
    const float* h_cat = (const float*)d_in[1];
    const float* Wq_a = (const float*)d_in[2];  const float* bq_a = (const float*)d_in[3];
    const float* Wk_a = (const float*)d_in[4];  const float* bk_a = (const float*)d_in[5];
    const float* Wv_a = (const float*)d_in[6];  const float* bv_a = (const float*)d_in[7];
    const float* Wq_c = (const float*)d_in[8];  const float* bq_c = (const float*)d_in[9];
    const float* Wk_c = (const float*)d_in[10]; const float* bk_c = (const float*)d_in[11];
    const float* Wv_c = (const float*)d_in[12]; const float* bv_c = (const float*)d_in[13];

    const int M_ads = in_sizes[0] / D;   // 8192
    const int M_cat = in_sizes[1] / D;   // 131072
    const int B     = M_ads / NA;        // 512

    float *qa, *ka, *va, *qc, *kc, *vc;
    cudaGetSymbolAddress((void**)&qa, g_qads);
    cudaGetSymbolAddress((void**)&ka, g_kads);
    cudaGetSymbolAddress((void**)&va, g_vads);
    cudaGetSymbolAddress((void**)&qc, g_qcat);
    cudaGetSymbolAddress((void**)&kc, g_kcat);
    cudaGetSymbolAddress((void**)&vc, g_vcat);
    __nv_bfloat16 *xah, *xal, *xch, *xcl, *wh, *wl;
    cudaGetSymbolAddress((void**)&xah, gx_ads_hi);
    cudaGetSymbolAddress((void**)&xal, gx_ads_lo);
    cudaGetSymbolAddress((void**)&xch, gx_cat_hi);
    cudaGetSymbolAddress((void**)&xcl, gx_cat_lo);
    cudaGetSymbolAddress((void**)&wh, gw_hi);
    cudaGetSymbolAddress((void**)&wl, gw_lo);

    // conversion prepass
    conv_x<<<512,  256>>>((const float4*)h_ads, (uint2*)xah, (uint2*)xal,
                          M_ads * D / 4);
    conv_x<<<4096, 256>>>((const float4*)h_cat, (uint2*)xch, (uint2*)xcl,
                          M_cat * D / 4);
    conv_w<<<dim3(64, 6), 256>>>(Wq_a, Wk_a, Wv_a, Wq_c, Wk_c, Wv_c,
                                 (uint2*)wh, (uint2*)wl);

    const int gemm_smem = 3 * SSTAGE;   // 98,304 B
    cudaFuncSetAttribute((const void*)gemm_pipe,
                         cudaFuncAttributeMaxDynamicSharedMemorySize, gemm_smem);

    gemm_pipe<<<dim3(M_ads / 128, 2, 3), 256, gemm_smem>>>(
        xah, xal, wh, wl, bq_a, bk_a, bv_a, qa, ka, va);
    gemm_pipe<<<dim3(M_cat / 128, 2, 3), 256, gemm_smem>>>(
        xch, xcl, wh + 3u * 65536u, wl + 3u * 65536u, bq_c, bk_c, bv_c, qc, kc, vc);

    const int attn_smem = 2 * 16 * 260 * 4;
    cudaFuncSetAttribute((const void*)attn_fused,
                         cudaFuncAttributeMaxDynamicSharedMemorySize, attn_smem);

    attn_fused<<<B + 8 * B, 256, attn_smem>>>(
        qa, kc, vc, h_ads, qc, ka, va, h_cat,
        (float*)d_out, (float*)d_out + (size_t)M_ads * D, B);
}

// round 8
// speedup vs baseline: 1.1839x; 1.1839x over previous
#include <cuda_runtime.h>
#include <cuda_fp16.h>
#include <math.h>
#include <stdint.h>

#define D   256
#define NA  16
#define NC  256

// ---------------------------------------------------------------------------
// Scratch (device globals — no allocation allowed in kernel_launch)
// ---------------------------------------------------------------------------
__device__ float g_qads[8192u  * 256u];
__device__ float g_kads[8192u  * 256u];
__device__ float g_vads[8192u  * 256u];
__device__ float g_qcat[131072u * 256u];
__device__ float g_kcat[131072u * 256u];
__device__ float g_vcat[131072u * 256u];
__device__ __half gx_ads_hi[8192u  * 256u];
__device__ __half gx_ads_lo[8192u  * 256u];
__device__ __half gx_cat_hi[131072u * 256u];
__device__ __half gx_cat_lo[131072u * 256u];
__device__ __half gw_hi[6u * 65536u];

// ---------------------------------------------------------------------------
// PTX helpers (arch-neutral sm_80+ — harness ptxas target is plain sm_103)
// ---------------------------------------------------------------------------
__device__ __forceinline__ uint32_t smem_u32(const void* p) {
    uint32_t a;
    asm("{ .reg .u64 t; cvta.to.shared.u64 t, %1; cvt.u32.u64 %0, t; }"
        : "=r"(a) : "l"(p));
    return a;
}
__device__ __forceinline__ void cpa16(uint32_t dst, const void* src) {
    asm volatile("cp.async.ca.shared.global [%0], [%1], 16;"
                 :: "r"(dst), "l"(src) : "memory");
}
__device__ __forceinline__ void ldm_x4(uint32_t* r, uint32_t addr) {
    asm volatile("ldmatrix.sync.aligned.m8n8.x4.shared.b16 {%0,%1,%2,%3}, [%4];"
                 : "=r"(r[0]), "=r"(r[1]), "=r"(r[2]), "=r"(r[3]) : "r"(addr));
}
__device__ __forceinline__ void mma16816h(float* c, const uint32_t* a,
                                          const uint32_t* b) {
    asm volatile(
        "mma.sync.aligned.m16n8k16.row.col.f32.f16.f16.f32 "
        "{%0,%1,%2,%3}, {%4,%5,%6,%7}, {%8,%9}, {%0,%1,%2,%3};"
        : "+f"(c[0]), "+f"(c[1]), "+f"(c[2]), "+f"(c[3])
        : "r"(a[0]), "r"(a[1]), "r"(a[2]), "r"(a[3]), "r"(b[0]), "r"(b[1]));
}
// split a,b (fp32) into packed fp16 hi pair + fp16 lo pair (lo = x - fp16(x))
__device__ __forceinline__ void split2h(float a, float b, uint32_t& hp, uint32_t& lp) {
    asm("cvt.rn.f16x2.f32 %0, %1, %2;" : "=r"(hp) : "f"(b), "f"(a));
    __half2 h2 = *reinterpret_cast<__half2*>(&hp);
    float af = __low2float(h2), bf = __high2float(h2);
    float la = a - af, lb = b - bf;
    asm("cvt.rn.f16x2.f32 %0, %1, %2;" : "=r"(lp) : "f"(lb), "f"(la));
}

// ---------------------------------------------------------------------------
// Conversion prepass: fp32 -> packed fp16 hi/lo (X), hi only (W)
// ---------------------------------------------------------------------------
__global__ void __launch_bounds__(256)
conv_x(const float4* __restrict__ src, uint2* __restrict__ hi,
       uint2* __restrict__ lo, int n4)
{
    for (int i = blockIdx.x * blockDim.x + threadIdx.x; i < n4;
         i += gridDim.x * blockDim.x) {
        float4 f = src[i];
        uint32_t h0, h1, l0, l1;
        split2h(f.x, f.y, h0, l0);
        split2h(f.z, f.w, h1, l1);
        hi[i] = make_uint2(h0, h1);
        lo[i] = make_uint2(l0, l1);
    }
}

__global__ void __launch_bounds__(256)
conv_w(const float* w0, const float* w1, const float* w2,
       const float* w3, const float* w4, const float* w5,
       uint2* __restrict__ hi)
{
    const int z = blockIdx.y;
    const float* W = (z == 0) ? w0 : (z == 1) ? w1 : (z == 2) ? w2
                   : (z == 3) ? w3 : (z == 4) ? w4 : w5;
    const int i = blockIdx.x * 256 + threadIdx.x;   // 0..16383
    float4 f = ((const float4*)W)[i];
    uint32_t h0, h1, l0, l1;
    split2h(f.x, f.y, h0, l0);
    split2h(f.z, f.w, h1, l1);
    hi[z * 16384 + i] = make_uint2(h0, h1);
}

// ---------------------------------------------------------------------------
// Pipelined fp16 GEMM: Y[M,256] = X @ W^T + bias (W z-fused: q/k/v)
// y = (xh + xl) * wh  — 2 MMA passes, dropped term |x*wl| ~ 2^-12.
// 256 thr / 8 warps (4m x 2n of 32x64), CTA tile 128x128, BK=64,
// 2-stage cp.async pipeline, 128B-row XOR swizzle, 1 sync per chunk (4 total).
// Stage = 3 matrices (Ahi|Alo|Bhi) x 128 rows x 128 B = 49,152 B.
// ---------------------------------------------------------------------------
#define SMAT   16384u
#define SSTAGE 49152u
#define SWZ(row, ch) ((uint32_t)(row) * 128u + (((uint32_t)((ch) ^ ((row) & 7)) & 7u) << 4))

__global__ void __launch_bounds__(256, 2)
gemm_pipe(const __half* __restrict__ Xhi, const __half* __restrict__ Xlo,
          const __half* __restrict__ Wh_all,
          const float* __restrict__ b0, const float* __restrict__ b1,
          const float* __restrict__ b2,
          float* __restrict__ Y0, float* __restrict__ Y1, float* __restrict__ Y2)
{
    const int z = blockIdx.z;
    const __half* Whi = Wh_all + (size_t)z * 65536;
    const float* bias = (z == 0) ? b0 : (z == 1) ? b1 : b2;
    float*       Y    = (z == 0) ? Y0 : (z == 1) ? Y1 : Y2;

    extern __shared__ __align__(16) char smraw[];
    const uint32_t sb = smem_u32(smraw);

    const int tid  = threadIdx.x;
    const int lane = tid & 31;
    const int wid  = tid >> 5;
    const int wm   = wid & 3;
    const int wn   = wid >> 2;
    const int m0   = blockIdx.x * 128;
    const int n0   = blockIdx.y * 128;

    float acc[2][8][4];
#pragma unroll
    for (int i = 0; i < 2; i++)
#pragma unroll
        for (int j = 0; j < 8; j++)
#pragma unroll
            for (int t = 0; t < 4; t++) acc[i][j][t] = 0.f;

    // copy coords: 1024 16B copies per matrix, 4 per thread per matrix
    // idx = tid + 256*i : row = idx>>3 (0..127), ch = idx&7 (0..7)
#define ISSUE(stage, kk)                                                          \
    do {                                                                          \
        const uint32_t s = sb + (stage) * SSTAGE;                                 \
        _Pragma("unroll")                                                         \
        for (int i = 0; i < 4; i++) {                                             \
            const int idx = tid + 256 * i;                                        \
            const int row = idx >> 3, ch = idx & 7;                               \
            const uint32_t d = SWZ(row, ch);                                      \
            cpa16(s + 0*SMAT + d, Xhi + (size_t)(m0 + row) * 256 + (kk) + ch * 8);\
            cpa16(s + 1*SMAT + d, Xlo + (size_t)(m0 + row) * 256 + (kk) + ch * 8);\
            cpa16(s + 2*SMAT + d, Whi + (size_t)(n0 + row) * 256 + (kk) + ch * 8);\
        }                                                                         \
        asm volatile("cp.async.commit_group;" ::: "memory");                      \
    } while (0)

    // per-lane ldmatrix row bases
    const int l15 = lane & 15, lhi = lane >> 4;
    uint32_t arowb[2], axor[2], browb[4], bxor[4];
#pragma unroll
    for (int i = 0; i < 2; i++) {
        uint32_t r = (uint32_t)(wm * 32 + i * 16 + l15);
        arowb[i] = r * 128u;
        axor[i] = r & 7u;
    }
#pragma unroll
    for (int bp = 0; bp < 4; bp++) {
        uint32_t r = (uint32_t)(wn * 64 + bp * 16 + l15);
        browb[bp] = r * 128u;
        bxor[bp] = r & 7u;
    }

    ISSUE(0, 0);

#pragma unroll 1
    for (int c = 0; c < 4; c++) {
        asm volatile("cp.async.wait_group 0;" ::: "memory");
        __syncthreads();
        if (c < 3) ISSUE((c + 1) & 1, (c + 1) * 64);

        const uint32_t st = sb + (uint32_t)(c & 1) * SSTAGE;
#pragma unroll
        for (int ks = 0; ks < 4; ks++) {
            const uint32_t cb = (uint32_t)(ks * 2 + lhi);   // 16B chunk 0..7
            uint32_t ah[2][4], al[2][4], b[8][2], r[4];

#pragma unroll
            for (int i = 0; i < 2; i++)
                ldm_x4(ah[i], st + 0*SMAT + arowb[i] + (((cb ^ axor[i]) & 7u) << 4));
#pragma unroll
            for (int bp = 0; bp < 4; bp++) {
                ldm_x4(r, st + 2*SMAT + browb[bp] + (((cb ^ bxor[bp]) & 7u) << 4));
                b[2*bp][0] = r[0]; b[2*bp+1][0] = r[1];
                b[2*bp][1] = r[2]; b[2*bp+1][1] = r[3];
            }
#pragma unroll
            for (int i = 0; i < 2; i++)
                ldm_x4(al[i], st + 1*SMAT + arowb[i] + (((cb ^ axor[i]) & 7u) << 4));

#pragma unroll
            for (int am = 0; am < 2; am++)
#pragma unroll
                for (int bn = 0; bn < 8; bn++) mma16816h(acc[am][bn], ah[am], b[bn]);
#pragma unroll
            for (int am = 0; am < 2; am++)
#pragma unroll
                for (int bn = 0; bn < 8; bn++) mma16816h(acc[am][bn], al[am], b[bn]);
        }
    }

    const int orow  = m0 + wm * 32 + (lane >> 2);
    const int ocol0 = n0 + wn * 64 + (lane & 3) * 2;
#pragma unroll
    for (int am = 0; am < 2; am++) {
#pragma unroll
        for (int bn = 0; bn < 8; bn++) {
            const int col = ocol0 + bn * 8;
            float2 bv = *(const float2*)(bias + col);
            float2 v0, v1;
            v0.x = acc[am][bn][0] + bv.x; v0.y = acc[am][bn][1] + bv.y;
            v1.x = acc[am][bn][2] + bv.x; v1.y = acc[am][bn][3] + bv.y;
            *(float2*)(Y + (size_t)(orow + am * 16)     * 256 + col) = v0;
            *(float2*)(Y + (size_t)(orow + am * 16 + 8) * 256 + col) = v1;
        }
    }
}

// ---------------------------------------------------------------------------
// Fused attention (unchanged). blockIdx.x < B -> ads, else cat. 256 threads.
// ---------------------------------------------------------------------------
__device__ __forceinline__ float dot8(float4 a0, float4 b0, float4 a1, float4 b1) {
    return a0.x*b0.x + a0.y*b0.y + a0.z*b0.z + a0.w*b0.w
         + a1.x*b1.x + a1.y*b1.y + a1.z*b1.z + a1.w*b1.w;
}

__device__ void ads_part(float* sm, int b,
                         const float* __restrict__ q, const float* __restrict__ k,
                         const float* __restrict__ v, const float* __restrict__ h,
                         float* __restrict__ out)
{
    float* Qs = sm;
    float* Ps = sm + 16 * 260;
    const int tid = threadIdx.x;
    const float scale = 0.0625f;

    {
        const float4* src = (const float4*)(q + (size_t)b * (NA * D));
#pragma unroll
        for (int h2 = 0; h2 < 4; h2++) {
            int i = tid + h2 * 256;
            int row = i >> 6, col = (i & 63) << 2;
            float4 vv = src[i];
            float* d = Qs + row * 260 + col;
            d[0] = vv.x; d[1] = vv.y; d[2] = vv.z; d[3] = vv.w;
        }
    }
    __syncthreads();

    const int w = tid >> 5, l = tid & 31;

#pragma unroll 1
    for (int bat = 0; bat < 8; bat++) {
        const int c0 = w * 32 + bat * 4;
        float4 kA[4], kB[4];
#pragma unroll
        for (int kk = 0; kk < 4; kk++) {
            const float* kr = k + ((size_t)b * NC + c0 + kk) * D;
            kA[kk] = *(const float4*)(kr + 4 * l);
            kB[kk] = *(const float4*)(kr + 128 + 4 * l);
        }
        float s[64];
#pragma unroll
        for (int i = 0; i < 64; i++) s[i] = 0.f;
#pragma unroll
        for (int j = 0; j < 16; j++) {
            float4 qA = *(const float4*)(Qs + j * 260 + 4 * l);
            float4 qB = *(const float4*)(Qs + j * 260 + 128 + 4 * l);
#pragma unroll
            for (int kk = 0; kk < 4; kk++)
                s[kk * 16 + j] += dot8(qA, kA[kk], qB, kB[kk]);
        }
#pragma unroll
        for (int off = 16; off > 0; off >>= 1)
#pragma unroll
            for (int i = 0; i < 64; i++)
                s[i] += __shfl_xor_sync(0xffffffffu, s[i], off);
        if (l < 16) {
#pragma unroll
            for (int kk = 0; kk < 4; kk++)
                Ps[l * 260 + c0 + kk] = s[kk * 16 + l] * scale;
        }
    }
    __syncthreads();

    {
        for (int r = w; r < 16; r += 8) {
            float* row = Ps + r * 260;
            float vals[8];
            float mx = -1e30f;
#pragma unroll
            for (int j = 0; j < 8; j++) { vals[j] = row[l + 32*j]; mx = fmaxf(mx, vals[j]); }
#pragma unroll
            for (int o = 16; o > 0; o >>= 1) mx = fmaxf(mx, __shfl_xor_sync(0xffffffffu, mx, o));
            float sum = 0.f;
#pragma unroll
            for (int j = 0; j < 8; j++) { vals[j] = __expf(vals[j] - mx); sum += vals[j]; }
#pragma unroll
            for (int o = 16; o > 0; o >>= 1) sum += __shfl_xor_sync(0xffffffffu, sum, o);
            float inv = 1.f / sum;
#pragma unroll
            for (int j = 0; j < 8; j++) row[l + 32*j] = vals[j] * inv;
        }
    }
    __syncthreads();

    const int aq = tid >> 6;
    const int dg = tid & 63;
    float4 u[4];
#pragma unroll
    for (int qi = 0; qi < 4; qi++) u[qi] = make_float4(0,0,0,0);
    const float* vbase = v + (size_t)b * NC * D + dg * 4;
    const float* prow0 = Ps + (aq * 4) * 260;
#pragma unroll 4
    for (int c = 0; c < 256; c++) {
        float4 vv = *(const float4*)(vbase + (size_t)c * D);
#pragma unroll
        for (int qi = 0; qi < 4; qi++) {
            float p = prow0[qi * 260 + c];
            u[qi].x += p * vv.x; u[qi].y += p * vv.y;
            u[qi].z += p * vv.z; u[qi].w += p * vv.w;
        }
    }

    float ssq[4];
#pragma unroll
    for (int qi = 0; qi < 4; qi++) {
        const float4 hv = *(const float4*)(h + ((size_t)b * NA + aq * 4 + qi) * D + dg * 4);
        u[qi].x += hv.x; u[qi].y += hv.y; u[qi].z += hv.z; u[qi].w += hv.w;
        ssq[qi] = u[qi].x*u[qi].x + u[qi].y*u[qi].y + u[qi].z*u[qi].z + u[qi].w*u[qi].w;
    }
#pragma unroll
    for (int off = 16; off > 0; off >>= 1)
#pragma unroll
        for (int qi = 0; qi < 4; qi++)
            ssq[qi] += __shfl_xor_sync(0xffffffffu, ssq[qi], off);
    if (l == 0) {
#pragma unroll
        for (int qi = 0; qi < 4; qi++) Qs[w * 4 + qi] = ssq[qi];
    }
    __syncthreads();
#pragma unroll
    for (int qi = 0; qi < 4; qi++) {
        float tot = Qs[(2 * aq) * 4 + qi] + Qs[(2 * aq + 1) * 4 + qi];
        float inv = 1.f / fmaxf(sqrtf(tot), 1e-12f);
        float4 o;
        o.x = u[qi].x * inv; o.y = u[qi].y * inv;
        o.z = u[qi].z * inv; o.w = u[qi].w * inv;
        *(float4*)(out + ((size_t)b * NA + aq * 4 + qi) * D + dg * 4) = o;
    }
}

__device__ void cat_part(float* sm, int idx,
                         const float* __restrict__ q, const float* __restrict__ k,
                         const float* __restrict__ v, const float* __restrict__ h,
                         float* __restrict__ out)
{
    float* Ks = sm;
    float* Vs = sm + 16 * 260;
    const int tid = threadIdx.x;
    const int b = idx >> 3, xp = idx & 7;
    const float scale = 0.0625f;

    {
        const float4* ks = (const float4*)(k + (size_t)b * (NA * D));
        const float4* vs = (const float4*)(v + (size_t)b * (NA * D));
#pragma unroll
        for (int h2 = 0; h2 < 4; h2++) {
            int i = tid + h2 * 256;
            int row = i >> 6, col = (i & 63) << 2;
            float4 kv = ks[i];
            float* dk = Ks + row * 260 + col;
            dk[0] = kv.x; dk[1] = kv.y; dk[2] = kv.z; dk[3] = kv.w;
            float4 vv = vs[i];
            float* dv = Vs + row * 260 + col;
            dv[0] = vv.x; dv[1] = vv.y; dv[2] = vv.z; dv[3] = vv.w;
        }
    }
    __syncthreads();

    const int w = tid >> 5, l = tid & 31;
    const int c0 = xp * 32 + w * 4;
    const size_t gr0 = (size_t)b * NC + c0;

    float4 qA[4], qB[4];
#pragma unroll
    for (int qi = 0; qi < 4; qi++) {
        const float* qr = q + (gr0 + qi) * D;
        qA[qi] = *(const float4*)(qr + 4 * l);
        qB[qi] = *(const float4*)(qr + 128 + 4 * l);
    }

    float s[64];
#pragma unroll
    for (int i = 0; i < 64; i++) s[i] = 0.f;
#pragma unroll
    for (int j = 0; j < 16; j++) {
        float4 kA = *(const float4*)(Ks + j * 260 + 4 * l);
        float4 kB = *(const float4*)(Ks + j * 260 + 128 + 4 * l);
#pragma unroll
        for (int qi = 0; qi < 4; qi++)
            s[qi * 16 + j] += dot8(qA[qi], kA, qB[qi], kB);
    }
#pragma unroll
    for (int off = 16; off > 0; off >>= 1)
#pragma unroll
        for (int i = 0; i < 64; i++)
            s[i] += __shfl_xor_sync(0xffffffffu, s[i], off);

#pragma unroll
    for (int qi = 0; qi < 4; qi++) {
        float mx = -1e30f;
#pragma unroll
        for (int j = 0; j < 16; j++) mx = fmaxf(mx, s[qi * 16 + j]);
        float sum = 0.f;
#pragma unroll
        for (int j = 0; j < 16; j++) {
            float e = __expf((s[qi * 16 + j] - mx) * scale);
            s[qi * 16 + j] = e; sum += e;
        }
        float inv = 1.f / sum;
#pragma unroll
        for (int j = 0; j < 16; j++) s[qi * 16 + j] *= inv;
    }

    float4 uA[4], uB[4];
#pragma unroll
    for (int qi = 0; qi < 4; qi++) { uA[qi] = make_float4(0,0,0,0); uB[qi] = uA[qi]; }
#pragma unroll
    for (int j = 0; j < 16; j++) {
        float4 vA = *(const float4*)(Vs + j * 260 + 4 * l);
        float4 vB = *(const float4*)(Vs + j * 260 + 128 + 4 * l);
#pragma unroll
        for (int qi = 0; qi < 4; qi++) {
            float p = s[qi * 16 + j];
            uA[qi].x += p * vA.x; uA[qi].y += p * vA.y;
            uA[qi].z += p * vA.z; uA[qi].w += p * vA.w;
            uB[qi].x += p * vB.x; uB[qi].y += p * vB.y;
            uB[qi].z += p * vB.z; uB[qi].w += p * vB.w;
        }
    }

#pragma unroll
    for (int qi = 0; qi < 4; qi++) {
        const float* hr = h + (gr0 + qi) * D;
        float4 rA = *(const float4*)(hr + 4 * l);
        float4 rB = *(const float4*)(hr + 128 + 4 * l);
        rA.x += uA[qi].x; rA.y += uA[qi].y; rA.z += uA[qi].z; rA.w += uA[qi].w;
        rB.x += uB[qi].x; rB.y += uB[qi].y; rB.z += uB[qi].z; rB.w += uB[qi].w;
        float nn = rA.x*rA.x + rA.y*rA.y + rA.z*rA.z + rA.w*rA.w
                 + rB.x*rB.x + rB.y*rB.y + rB.z*rB.z + rB.w*rB.w;
#pragma unroll
        for (int o = 16; o > 0; o >>= 1) nn += __shfl_xor_sync(0xffffffffu, nn, o);
        float inv = 1.f / fmaxf(sqrtf(nn), 1e-12f);
        float* orow = out + (gr0 + qi) * D;
        *(float4*)(orow + 4 * l) =
            make_float4(rA.x*inv, rA.y*inv, rA.z*inv, rA.w*inv);
        *(float4*)(orow + 128 + 4 * l) =
            make_float4(rB.x*inv, rB.y*inv, rB.z*inv, rB.w*inv);
    }
}

__global__ void __launch_bounds__(256)
attn_fused(const float* qa, const float* kc, const float* vc, const float* hA,
           const float* qc, const float* ka, const float* va, const float* hC,
           float* outA, float* outC, int B)
{
    extern __shared__ __align__(16) float sm[];
    if ((int)blockIdx.x < B)
        ads_part(sm, blockIdx.x, qa, kc, vc, hA, outA);
    else
        cat_part(sm, blockIdx.x - B, qc, ka, va, hC, outC);
}

// ---------------------------------------------------------------------------
// Launch
// ---------------------------------------------------------------------------
extern "C" void kernel_launch(void* const* d_in, const int* in_sizes, int n_in,
                              void* d_out, int out_size)
{
    const float* h_ads = (const float*)d_in[0];
    const float* h_cat = (const float*)d_in[1];
    const float* Wq_a = (const float*)d_in[2];  const float* bq_a = (const float*)d_in[3];
    const float* Wk_a = (const float*)d_in[4];  const float* bk_a = (const float*)d_in[5];
    const float* Wv_a = (const float*)d_in[6];  const float* bv_a = (const float*)d_in[7];
    const float* Wq_c = (const float*)d_in[8];  const float* bq_c = (const float*)d_in[9];
    const float* Wk_c = (const float*)d_in[10]; const float* bk_c = (const float*)d_in[11];
    const float* Wv_c = (const float*)d_in[12]; const float* bv_c = (const float*)d_in[13];

    const int M_ads = in_sizes[0] / D;   // 8192
    const int M_cat = in_sizes[1] / D;   // 131072
    const int B     = M_ads / NA;        // 512

    float *qa, *ka, *va, *qc, *kc, *vc;
    cudaGetSymbolAddress((void**)&qa, g_qads);
    cudaGetSymbolAddress((void**)&ka, g_kads);
    cudaGetSymbolAddress((void**)&va, g_vads);
    cudaGetSymbolAddress((void**)&qc, g_qcat);
    cudaGetSymbolAddress((void**)&kc, g_kcat);
    cudaGetSymbolAddress((void**)&vc, g_vcat);
    __half *xah, *xal, *xch, *xcl, *wh;
    cudaGetSymbolAddress((void**)&xah, gx_ads_hi);
    cudaGetSymbolAddress((void**)&xal, gx_ads_lo);
    cudaGetSymbolAddress((void**)&xch, gx_cat_hi);
    cudaGetSymbolAddress((void**)&xcl, gx_cat_lo);
    cudaGetSymbolAddress((void**)&wh, gw_hi);

    // conversion prepass
    conv_x<<<512,  256>>>((const float4*)h_ads, (uint2*)xah, (uint2*)xal,
                          M_ads * D / 4);
    conv_x<<<4096, 256>>>((const float4*)h_cat, (uint2*)xch, (uint2*)xcl,
                          M_cat * D / 4);
    conv_w<<<dim3(64, 6), 256>>>(Wq_a, Wk_a, Wv_a, Wq_c, Wk_c, Wv_c, (uint2*)wh);

    const int gemm_smem = 2 * SSTAGE;   // 98,304 B
    cudaFuncSetAttribute((const void*)gemm_pipe,
                         cudaFuncAttributeMaxDynamicSharedMemorySize, gemm_smem);

    gemm_pipe<<<dim3(M_ads / 128, 2, 3), 256, gemm_smem>>>(
        xah, xal, wh, bq_a, bk_a, bv_a, qa, ka, va);
    gemm_pipe<<<dim3(M_cat / 128, 2, 3), 256, gemm_smem>>>(
        xch, xcl, wh + 3u * 65536u, bq_c, bk_c, bv_c, qc, kc, vc);

    const int attn_smem = 2 * 16 * 260 * 4;
    cudaFuncSetAttribute((const void*)attn_fused,
                         cudaFuncAttributeMaxDynamicSharedMemorySize, attn_smem);

    attn_fused<<<B + 8 * B, 256, attn_smem>>>(
        qa, kc, vc, h_ads, qc, ka, va, h_cat,
        (float*)d_out, (float*)d_out + (size_t)M_ads * D, B);
}

// round 9
// speedup vs baseline: 1.3981x; 1.1810x over previous
#include <cuda_runtime.h>
#include <cuda_fp16.h>
#include <math.h>
#include <stdint.h>

#define D   256
#define NA  16
#define NC  256

// ---------------------------------------------------------------------------
// Scratch (device globals — no allocation allowed in kernel_launch)
// ---------------------------------------------------------------------------
__device__ float g_qads[8192u  * 256u];
__device__ float g_kads[8192u  * 256u];
__device__ float g_vads[8192u  * 256u];
__device__ float g_qcat[131072u * 256u];
__device__ float g_kcat[131072u * 256u];
__device__ float g_vcat[131072u * 256u];
__device__ __half gx_ads[8192u  * 256u];
__device__ __half gx_cat[131072u * 256u];
__device__ __half gw_hi[6u * 65536u];

// ---------------------------------------------------------------------------
// PTX helpers (arch-neutral sm_80+ — harness ptxas target is plain sm_103)
// ---------------------------------------------------------------------------
__device__ __forceinline__ uint32_t smem_u32(const void* p) {
    uint32_t a;
    asm("{ .reg .u64 t; cvta.to.shared.u64 t, %1; cvt.u32.u64 %0, t; }"
        : "=r"(a) : "l"(p));
    return a;
}
__device__ __forceinline__ void cpa16(uint32_t dst, const void* src) {
    asm volatile("cp.async.ca.shared.global [%0], [%1], 16;"
                 :: "r"(dst), "l"(src) : "memory");
}
__device__ __forceinline__ void ldm_x4(uint32_t* r, uint32_t addr) {
    asm volatile("ldmatrix.sync.aligned.m8n8.x4.shared.b16 {%0,%1,%2,%3}, [%4];"
                 : "=r"(r[0]), "=r"(r[1]), "=r"(r[2]), "=r"(r[3]) : "r"(addr));
}
__device__ __forceinline__ void mma16816h(float* c, const uint32_t* a,
                                          const uint32_t* b) {
    asm volatile(
        "mma.sync.aligned.m16n8k16.row.col.f32.f16.f16.f32 "
        "{%0,%1,%2,%3}, {%4,%5,%6,%7}, {%8,%9}, {%0,%1,%2,%3};"
        : "+f"(c[0]), "+f"(c[1]), "+f"(c[2]), "+f"(c[3])
        : "r"(a[0]), "r"(a[1]), "r"(a[2]), "r"(a[3]), "r"(b[0]), "r"(b[1]));
}
__device__ __forceinline__ uint32_t cvt2h(float a, float b) {
    uint32_t hp;
    asm("cvt.rn.f16x2.f32 %0, %1, %2;" : "=r"(hp) : "f"(b), "f"(a));
    return hp;
}

// ---------------------------------------------------------------------------
// Conversion prepass: fp32 -> packed fp16
// ---------------------------------------------------------------------------
__global__ void __launch_bounds__(256)
conv_x(const float4* __restrict__ src, uint2* __restrict__ hi, int n4)
{
    for (int i = blockIdx.x * blockDim.x + threadIdx.x; i < n4;
         i += gridDim.x * blockDim.x) {
        float4 f = src[i];
        hi[i] = make_uint2(cvt2h(f.x, f.y), cvt2h(f.z, f.w));
    }
}

__global__ void __launch_bounds__(256)
conv_w(const float* w0, const float* w1, const float* w2,
       const float* w3, const float* w4, const float* w5,
       uint2* __restrict__ hi)
{
    const int z = blockIdx.y;
    const float* W = (z == 0) ? w0 : (z == 1) ? w1 : (z == 2) ? w2
                   : (z == 3) ? w3 : (z == 4) ? w4 : w5;
    const int i = blockIdx.x * 256 + threadIdx.x;   // 0..16383
    float4 f = ((const float4*)W)[i];
    hi[z * 16384 + i] = make_uint2(cvt2h(f.x, f.y), cvt2h(f.z, f.w));
}

// ---------------------------------------------------------------------------
// Pipelined fp16 GEMM: Y[M,256] = fp16(X) @ fp16(W)^T + bias (W z-fused q/k/v)
// Single pass: rel err ~5e-5 (measured anchor: 2-pass = 3.06e-5).
// 256 thr / 8 warps (4m x 2n of 32x64), CTA tile 128x128, BK=64,
// 3-stage cp.async pipeline, 128B-row XOR swizzle, 1 sync per chunk (4 total).
// Stage = 2 matrices (A|B) x 128 rows x 128 B = 32,768 B; 3 stages = 96 KB.
// ---------------------------------------------------------------------------
#define SMAT   16384u
#define SSTAGE 32768u
#define SWZ(row, ch) ((uint32_t)(row) * 128u + (((uint32_t)((ch) ^ ((row) & 7)) & 7u) << 4))

__global__ void __launch_bounds__(256, 2)
gemm_pipe(const __half* __restrict__ Xh, const __half* __restrict__ Wh_all,
          const float* __restrict__ b0, const float* __restrict__ b1,
          const float* __restrict__ b2,
          float* __restrict__ Y0, float* __restrict__ Y1, float* __restrict__ Y2)
{
    const int z = blockIdx.z;
    const __half* Whi = Wh_all + (size_t)z * 65536;
    const float* bias = (z == 0) ? b0 : (z == 1) ? b1 : b2;
    float*       Y    = (z == 0) ? Y0 : (z == 1) ? Y1 : Y2;

    extern __shared__ __align__(16) char smraw[];
    const uint32_t sb = smem_u32(smraw);

    const int tid  = threadIdx.x;
    const int lane = tid & 31;
    const int wid  = tid >> 5;
    const int wm   = wid & 3;
    const int wn   = wid >> 2;
    const int m0   = blockIdx.x * 128;
    const int n0   = blockIdx.y * 128;

    float acc[2][8][4];
#pragma unroll
    for (int i = 0; i < 2; i++)
#pragma unroll
        for (int j = 0; j < 8; j++)
#pragma unroll
            for (int t = 0; t < 4; t++) acc[i][j][t] = 0.f;

    // copy coords: 1024 16B copies per matrix, 4 per thread per matrix
#define ISSUE(stage, kk)                                                          \
    do {                                                                          \
        const uint32_t s = sb + (stage) * SSTAGE;                                 \
        _Pragma("unroll")                                                         \
        for (int i = 0; i < 4; i++) {                                             \
            const int idx = tid + 256 * i;                                        \
            const int row = idx >> 3, ch = idx & 7;                               \
            const uint32_t d = SWZ(row, ch);                                      \
            cpa16(s + 0*SMAT + d, Xh  + (size_t)(m0 + row) * 256 + (kk) + ch * 8);\
            cpa16(s + 1*SMAT + d, Whi + (size_t)(n0 + row) * 256 + (kk) + ch * 8);\
        }                                                                         \
        asm volatile("cp.async.commit_group;" ::: "memory");                      \
    } while (0)

    // per-lane ldmatrix row bases
    const int l15 = lane & 15, lhi = lane >> 4;
    uint32_t arowb[2], axor[2], browb[4], bxor[4];
#pragma unroll
    for (int i = 0; i < 2; i++) {
        uint32_t r = (uint32_t)(wm * 32 + i * 16 + l15);
        arowb[i] = r * 128u;
        axor[i] = r & 7u;
    }
#pragma unroll
    for (int bp = 0; bp < 4; bp++) {
        uint32_t r = (uint32_t)(wn * 64 + bp * 16 + l15);
        browb[bp] = r * 128u;
        bxor[bp] = r & 7u;
    }

    ISSUE(0, 0);
    ISSUE(1, 64);

#pragma unroll 1
    for (int c = 0; c < 4; c++) {
        if (c < 3)
            asm volatile("cp.async.wait_group 1;" ::: "memory");
        else
            asm volatile("cp.async.wait_group 0;" ::: "memory");
        __syncthreads();
        if (c + 2 < 4) ISSUE((c + 2) % 3, (c + 2) * 64);

        const uint32_t st = sb + (uint32_t)(c % 3) * SSTAGE;
#pragma unroll
        for (int ks = 0; ks < 4; ks++) {
            const uint32_t cb = (uint32_t)(ks * 2 + lhi);   // 16B chunk 0..7
            uint32_t ah[2][4], b[8][2], r[4];

#pragma unroll
            for (int i = 0; i < 2; i++)
                ldm_x4(ah[i], st + 0*SMAT + arowb[i] + (((cb ^ axor[i]) & 7u) << 4));
#pragma unroll
            for (int bp = 0; bp < 4; bp++) {
                ldm_x4(r, st + 1*SMAT + browb[bp] + (((cb ^ bxor[bp]) & 7u) << 4));
                b[2*bp][0] = r[0]; b[2*bp+1][0] = r[1];
                b[2*bp][1] = r[2]; b[2*bp+1][1] = r[3];
            }
#pragma unroll
            for (int am = 0; am < 2; am++)
#pragma unroll
                for (int bn = 0; bn < 8; bn++) mma16816h(acc[am][bn], ah[am], b[bn]);
        }
    }

    const int orow  = m0 + wm * 32 + (lane >> 2);
    const int ocol0 = n0 + wn * 64 + (lane & 3) * 2;
#pragma unroll
    for (int am = 0; am < 2; am++) {
#pragma unroll
        for (int bn = 0; bn < 8; bn++) {
            const int col = ocol0 + bn * 8;
            float2 bv = *(const float2*)(bias + col);
            float2 v0, v1;
            v0.x = acc[am][bn][0] + bv.x; v0.y = acc[am][bn][1] + bv.y;
            v1.x = acc[am][bn][2] + bv.x; v1.y = acc[am][bn][3] + bv.y;
            *(float2*)(Y + (size_t)(orow + am * 16)     * 256 + col) = v0;
            *(float2*)(Y + (size_t)(orow + am * 16 + 8) * 256 + col) = v1;
        }
    }
}

// ---------------------------------------------------------------------------
// Fused attention (unchanged). blockIdx.x < B -> ads, else cat. 256 threads.
// ---------------------------------------------------------------------------
__device__ __forceinline__ float dot8(float4 a0, float4 b0, float4 a1, float4 b1) {
    return a0.x*b0.x + a0.y*b0.y + a0.z*b0.z + a0.w*b0.w
         + a1.x*b1.x + a1.y*b1.y + a1.z*b1.z + a1.w*b1.w;
}

__device__ void ads_part(float* sm, int b,
                         const float* __restrict__ q, const float* __restrict__ k,
                         const float* __restrict__ v, const float* __restrict__ h,
                         float* __restrict__ out)
{
    float* Qs = sm;
    float* Ps = sm + 16 * 260;
    const int tid = threadIdx.x;
    const float scale = 0.0625f;

    {
        const float4* src = (const float4*)(q + (size_t)b * (NA * D));
#pragma unroll
        for (int h2 = 0; h2 < 4; h2++) {
            int i = tid + h2 * 256;
            int row = i >> 6, col = (i & 63) << 2;
            float4 vv = src[i];
            float* d = Qs + row * 260 + col;
            d[0] = vv.x; d[1] = vv.y; d[2] = vv.z; d[3] = vv.w;
        }
    }
    __syncthreads();

    const int w = tid >> 5, l = tid & 31;

#pragma unroll 1
    for (int bat = 0; bat < 8; bat++) {
        const int c0 = w * 32 + bat * 4;
        float4 kA[4], kB[4];
#pragma unroll
        for (int kk = 0; kk < 4; kk++) {
            const float* kr = k + ((size_t)b * NC + c0 + kk) * D;
            kA[kk] = *(const float4*)(kr + 4 * l);
            kB[kk] = *(const float4*)(kr + 128 + 4 * l);
        }
        float s[64];
#pragma unroll
        for (int i = 0; i < 64; i++) s[i] = 0.f;
#pragma unroll
        for (int j = 0; j < 16; j++) {
            float4 qA = *(const float4*)(Qs + j * 260 + 4 * l);
            float4 qB = *(const float4*)(Qs + j * 260 + 128 + 4 * l);
#pragma unroll
            for (int kk = 0; kk < 4; kk++)
                s[kk * 16 + j] += dot8(qA, kA[kk], qB, kB[kk]);
        }
#pragma unroll
        for (int off = 16; off > 0; off >>= 1)
#pragma unroll
            for (int i = 0; i < 64; i++)
                s[i] += __shfl_xor_sync(0xffffffffu, s[i], off);
        if (l < 16) {
#pragma unroll
            for (int kk = 0; kk < 4; kk++)
                Ps[l * 260 + c0 + kk] = s[kk * 16 + l] * scale;
        }
    }
    __syncthreads();

    {
        for (int r = w; r < 16; r += 8) {
            float* row = Ps + r * 260;
            float vals[8];
            float mx = -1e30f;
#pragma unroll
            for (int j = 0; j < 8; j++) { vals[j] = row[l + 32*j]; mx = fmaxf(mx, vals[j]); }
#pragma unroll
            for (int o = 16; o > 0; o >>= 1) mx = fmaxf(mx, __shfl_xor_sync(0xffffffffu, mx, o));
            float sum = 0.f;
#pragma unroll
            for (int j = 0; j < 8; j++) { vals[j] = __expf(vals[j] - mx); sum += vals[j]; }
#pragma unroll
            for (int o = 16; o > 0; o >>= 1) sum += __shfl_xor_sync(0xffffffffu, sum, o);
            float inv = 1.f / sum;
#pragma unroll
            for (int j = 0; j < 8; j++) row[l + 32*j] = vals[j] * inv;
        }
    }
    __syncthreads();

    const int aq = tid >> 6;
    const int dg = tid & 63;
    float4 u[4];
#pragma unroll
    for (int qi = 0; qi < 4; qi++) u[qi] = make_float4(0,0,0,0);
    const float* vbase = v + (size_t)b * NC * D + dg * 4;
    const float* prow0 = Ps + (aq * 4) * 260;
#pragma unroll 4
    for (int c = 0; c < 256; c++) {
        float4 vv = *(const float4*)(vbase + (size_t)c * D);
#pragma unroll
        for (int qi = 0; qi < 4; qi++) {
            float p = prow0[qi * 260 + c];
            u[qi].x += p * vv.x; u[qi].y += p * vv.y;
            u[qi].z += p * vv.z; u[qi].w += p * vv.w;
        }
    }

    float ssq[4];
#pragma unroll
    for (int qi = 0; qi < 4; qi++) {
        const float4 hv = *(const float4*)(h + ((size_t)b * NA + aq * 4 + qi) * D + dg * 4);
        u[qi].x += hv.x; u[qi].y += hv.y; u[qi].z += hv.z; u[qi].w += hv.w;
        ssq[qi] = u[qi].x*u[qi].x + u[qi].y*u[qi].y + u[qi].z*u[qi].z + u[qi].w*u[qi].w;
    }
#pragma unroll
    for (int off = 16; off > 0; off >>= 1)
#pragma unroll
        for (int qi = 0; qi < 4; qi++)
            ssq[qi] += __shfl_xor_sync(0xffffffffu, ssq[qi], off);
    if (l == 0) {
#pragma unroll
        for (int qi = 0; qi < 4; qi++) Qs[w * 4 + qi] = ssq[qi];
    }
    __syncthreads();
#pragma unroll
    for (int qi = 0; qi < 4; qi++) {
        float tot = Qs[(2 * aq) * 4 + qi] + Qs[(2 * aq + 1) * 4 + qi];
        float inv = 1.f / fmaxf(sqrtf(tot), 1e-12f);
        float4 o;
        o.x = u[qi].x * inv; o.y = u[qi].y * inv;
        o.z = u[qi].z * inv; o.w = u[qi].w * inv;
        *(float4*)(out + ((size_t)b * NA + aq * 4 + qi) * D + dg * 4) = o;
    }
}

__device__ void cat_part(float* sm, int idx,
                         const float* __restrict__ q, const float* __restrict__ k,
                         const float* __restrict__ v, const float* __restrict__ h,
                         float* __restrict__ out)
{
    float* Ks = sm;
    float* Vs = sm + 16 * 260;
    const int tid = threadIdx.x;
    const int b = idx >> 3, xp = idx & 7;
    const float scale = 0.0625f;

    {
        const float4* ks = (const float4*)(k + (size_t)b * (NA * D));
        const float4* vs = (const float4*)(v + (size_t)b * (NA * D));
#pragma unroll
        for (int h2 = 0; h2 < 4; h2++) {
            int i = tid + h2 * 256;
            int row = i >> 6, col = (i & 63) << 2;
            float4 kv = ks[i];
            float* dk = Ks + row * 260 + col;
            dk[0] = kv.x; dk[1] = kv.y; dk[2] = kv.z; dk[3] = kv.w;
            float4 vv = vs[i];
            float* dv = Vs + row * 260 + col;
            dv[0] = vv.x; dv[1] = vv.y; dv[2] = vv.z; dv[3] = vv.w;
        }
    }
    __syncthreads();

    const int w = tid >> 5, l = tid & 31;
    const int c0 = xp * 32 + w * 4;
    const size_t gr0 = (size_t)b * NC + c0;

    float4 qA[4], qB[4];
#pragma unroll
    for (int qi = 0; qi < 4; qi++) {
        const float* qr = q + (gr0 + qi) * D;
        qA[qi] = *(const float4*)(qr + 4 * l);
        qB[qi] = *(const float4*)(qr + 128 + 4 * l);
    }

    float s[64];
#pragma unroll
    for (int i = 0; i < 64; i++) s[i] = 0.f;
#pragma unroll
    for (int j = 0; j < 16; j++) {
        float4 kA = *(const float4*)(Ks + j * 260 + 4 * l);
        float4 kB = *(const float4*)(Ks + j * 260 + 128 + 4 * l);
#pragma unroll
        for (int qi = 0; qi < 4; qi++)
            s[qi * 16 + j] += dot8(qA[qi], kA, qB[qi], kB);
    }
#pragma unroll
    for (int off = 16; off > 0; off >>= 1)
#pragma unroll
        for (int i = 0; i < 64; i++)
            s[i] += __shfl_xor_sync(0xffffffffu, s[i], off);

#pragma unroll
    for (int qi = 0; qi < 4; qi++) {
        float mx = -1e30f;
#pragma unroll
        for (int j = 0; j < 16; j++) mx = fmaxf(mx, s[qi * 16 + j]);
        float sum = 0.f;
#pragma unroll
        for (int j = 0; j < 16; j++) {
            float e = __expf((s[qi * 16 + j] - mx) * scale);
            s[qi * 16 + j] = e; sum += e;
        }
        float inv = 1.f / sum;
#pragma unroll
        for (int j = 0; j < 16; j++) s[qi * 16 + j] *= inv;
    }

    float4 uA[4], uB[4];
#pragma unroll
    for (int qi = 0; qi < 4; qi++) { uA[qi] = make_float4(0,0,0,0); uB[qi] = uA[qi]; }
#pragma unroll
    for (int j = 0; j < 16; j++) {
        float4 vA = *(const float4*)(Vs + j * 260 + 4 * l);
        float4 vB = *(const float4*)(Vs + j * 260 + 128 + 4 * l);
#pragma unroll
        for (int qi = 0; qi < 4; qi++) {
            float p = s[qi * 16 + j];
            uA[qi].x += p * vA.x; uA[qi].y += p * vA.y;
            uA[qi].z += p * vA.z; uA[qi].w += p * vA.w;
            uB[qi].x += p * vB.x; uB[qi].y += p * vB.y;
            uB[qi].z += p * vB.z; uB[qi].w += p * vB.w;
        }
    }

#pragma unroll
    for (int qi = 0; qi < 4; qi++) {
        const float* hr = h + (gr0 + qi) * D;
        float4 rA = *(const float4*)(hr + 4 * l);
        float4 rB = *(const float4*)(hr + 128 + 4 * l);
        rA.x += uA[qi].x; rA.y += uA[qi].y; rA.z += uA[qi].z; rA.w += uA[qi].w;
        rB.x += uB[qi].x; rB.y += uB[qi].y; rB.z += uB[qi].z; rB.w += uB[qi].w;
        float nn = rA.x*rA.x + rA.y*rA.y + rA.z*rA.z + rA.w*rA.w
                 + rB.x*rB.x + rB.y*rB.y + rB.z*rB.z + rB.w*rB.w;
#pragma unroll
        for (int o = 16; o > 0; o >>= 1) nn += __shfl_xor_sync(0xffffffffu, nn, o);
        float inv = 1.f / fmaxf(sqrtf(nn), 1e-12f);
        float* orow = out + (gr0 + qi) * D;
        *(float4*)(orow + 4 * l) =
            make_float4(rA.x*inv, rA.y*inv, rA.z*inv, rA.w*inv);
        *(float4*)(orow + 128 + 4 * l) =
            make_float4(rB.x*inv, rB.y*inv, rB.z*inv, rB.w*inv);
    }
}

__global__ void __launch_bounds__(256)
attn_fused(const float* qa, const float* kc, const float* vc, const float* hA,
           const float* qc, const float* ka, const float* va, const float* hC,
           float* outA, float* outC, int B)
{
    extern __shared__ __align__(16) float sm[];
    if ((int)blockIdx.x < B)
        ads_part(sm, blockIdx.x, qa, kc, vc, hA, outA);
    else
        cat_part(sm, blockIdx.x - B, qc, ka, va, hC, outC);
}

// ---------------------------------------------------------------------------
// Launch
// ---------------------------------------------------------------------------
extern "C" void kernel_launch(void* const* d_in, const int* in_sizes, int n_in,
                              void* d_out, int out_size)
{
    const float* h_ads = (const float*)d_in[0];
    const float* h_cat = (const float*)d_in[1];
    const float* Wq_a = (const float*)d_in[2];  const float* bq_a = (const float*)d_in[3];
    const float* Wk_a = (const float*)d_in[4];  const float* bk_a = (const float*)d_in[5];
    const float* Wv_a = (const float*)d_in[6];  const float* bv_a = (const float*)d_in[7];
    const float* Wq_c = (const float*)d_in[8];  const float* bq_c = (const float*)d_in[9];
    const float* Wk_c = (const float*)d_in[10]; const float* bk_c = (const float*)d_in[11];
    const float* Wv_c = (const float*)d_in[12]; const float* bv_c = (const float*)d_in[13];

    const int M_ads = in_sizes[0] / D;   // 8192
    const int M_cat = in_sizes[1] / D;   // 131072
    const int B     = M_ads / NA;        // 512

    float *qa, *ka, *va, *qc, *kc, *vc;
    cudaGetSymbolAddress((void**)&qa, g_qads);
    cudaGetSymbolAddress((void**)&ka, g_kads);
    cudaGetSymbolAddress((void**)&va, g_vads);
    cudaGetSymbolAddress((void**)&qc, g_qcat);
    cudaGetSymbolAddress((void**)&kc, g_kcat);
    cudaGetSymbolAddress((void**)&vc, g_vcat);
    __half *xah, *xch, *wh;
    cudaGetSymbolAddress((void**)&xah, gx_ads);
    cudaGetSymbolAddress((void**)&xch, gx_cat);
    cudaGetSymbolAddress((void**)&wh, gw_hi);

    // conversion prepass
    conv_x<<<512,  256>>>((const float4*)h_ads, (uint2*)xah, M_ads * D / 4);
    conv_x<<<4096, 256>>>((const float4*)h_cat, (uint2*)xch, M_cat * D / 4);
    conv_w<<<dim3(64, 6), 256>>>(Wq_a, Wk_a, Wv_a, Wq_c, Wk_c, Wv_c, (uint2*)wh);

    const int gemm_smem = 3 * SSTAGE;   // 98,304 B
    cudaFuncSetAttribute((const void*)gemm_pipe,
                         cudaFuncAttributeMaxDynamicSharedMemorySize, gemm_smem);

    gemm_pipe<<<dim3(M_ads / 128, 2, 3), 256, gemm_smem>>>(
        xah, wh, bq_a, bk_a, bv_a, qa, ka, va);
    gemm_pipe<<<dim3(M_cat / 128, 2, 3), 256, gemm_smem>>>(
        xch, wh + 3u * 65536u, bq_c, bk_c, bv_c, qc, kc, vc);

    const int attn_smem = 2 * 16 * 260 * 4;
    cudaFuncSetAttribute((const void*)attn_fused,
                         cudaFuncAttributeMaxDynamicSharedMemorySize, attn_smem);

    attn_fused<<<B + 8 * B, 256, attn_smem>>>(
        qa, kc, vc, h_ads, qc, ka, va, h_cat,
        (float*)d_out, (float*)d_out + (size_t)M_ads * D, B);
}

// round 10
// speedup vs baseline: 1.4463x; 1.0344x over previous
#include <cuda_runtime.h>
#include <cuda_fp16.h>
#include <math.h>
#include <stdint.h>

#define D   256
#define NA  16
#define NC  256

// ---------------------------------------------------------------------------
// Scratch (device globals — no allocation allowed in kernel_launch)
// ---------------------------------------------------------------------------
__device__ __half g_qads[8192u  * 256u];
__device__ __half g_kads[8192u  * 256u];
__device__ __half g_vads[8192u  * 256u];
__device__ __half g_qcat[131072u * 256u];
__device__ __half g_kcat[131072u * 256u];
__device__ __half g_vcat[131072u * 256u];
__device__ __half gx_ads[8192u  * 256u];
__device__ __half gx_cat[131072u * 256u];
__device__ __half gw_hi[6u * 65536u];

// ---------------------------------------------------------------------------
// PTX helpers (arch-neutral sm_80+ — harness ptxas target is plain sm_103)
// ---------------------------------------------------------------------------
__device__ __forceinline__ uint32_t smem_u32(const void* p) {
    uint32_t a;
    asm("{ .reg .u64 t; cvta.to.shared.u64 t, %1; cvt.u32.u64 %0, t; }"
        : "=r"(a) : "l"(p));
    return a;
}
__device__ __forceinline__ void cpa16(uint32_t dst, const void* src) {
    asm volatile("cp.async.ca.shared.global [%0], [%1], 16;"
                 :: "r"(dst), "l"(src) : "memory");
}
__device__ __forceinline__ void ldm_x4(uint32_t* r, uint32_t addr) {
    asm volatile("ldmatrix.sync.aligned.m8n8.x4.shared.b16 {%0,%1,%2,%3}, [%4];"
                 : "=r"(r[0]), "=r"(r[1]), "=r"(r[2]), "=r"(r[3]) : "r"(addr));
}
__device__ __forceinline__ void mma16816h(float* c, const uint32_t* a,
                                          const uint32_t* b) {
    asm volatile(
        "mma.sync.aligned.m16n8k16.row.col.f32.f16.f16.f32 "
        "{%0,%1,%2,%3}, {%4,%5,%6,%7}, {%8,%9}, {%0,%1,%2,%3};"
        : "+f"(c[0]), "+f"(c[1]), "+f"(c[2]), "+f"(c[3])
        : "r"(a[0]), "r"(a[1]), "r"(a[2]), "r"(a[3]), "r"(b[0]), "r"(b[1]));
}
// pack (a -> low, b -> high)
__device__ __forceinline__ uint32_t cvt2h(float a, float b) {
    uint32_t hp;
    asm("cvt.rn.f16x2.f32 %0, %1, %2;" : "=r"(hp) : "f"(b), "f"(a));
    return hp;
}
// unpack 4 halves -> float4
__device__ __forceinline__ float4 h4f(uint2 v) {
    __half2 h0 = *reinterpret_cast<__half2*>(&v.x);
    __half2 h1 = *reinterpret_cast<__half2*>(&v.y);
    float2 f0 = __half22float2(h0), f1 = __half22float2(h1);
    return make_float4(f0.x, f0.y, f1.x, f1.y);
}

// ---------------------------------------------------------------------------
// Conversion prepass: fp32 -> packed fp16
// ---------------------------------------------------------------------------
__global__ void __launch_bounds__(256)
conv_x(const float4* __restrict__ src, uint2* __restrict__ hi, int n4)
{
    for (int i = blockIdx.x * blockDim.x + threadIdx.x; i < n4;
         i += gridDim.x * blockDim.x) {
        float4 f = src[i];
        hi[i] = make_uint2(cvt2h(f.x, f.y), cvt2h(f.z, f.w));
    }
}

__global__ void __launch_bounds__(256)
conv_w(const float* w0, const float* w1, const float* w2,
       const float* w3, const float* w4, const float* w5,
       uint2* __restrict__ hi)
{
    const int z = blockIdx.y;
    const float* W = (z == 0) ? w0 : (z == 1) ? w1 : (z == 2) ? w2
                   : (z == 3) ? w3 : (z == 4) ? w4 : w5;
    const int i = blockIdx.x * 256 + threadIdx.x;   // 0..16383
    float4 f = ((const float4*)W)[i];
    hi[z * 16384 + i] = make_uint2(cvt2h(f.x, f.y), cvt2h(f.z, f.w));
}

// ---------------------------------------------------------------------------
// Pipelined fp16 GEMM: Y[M,256] = fp16(X) @ fp16(W)^T + bias, fp16 output.
// 256 thr / 8 warps (4m x 2n of 32x64), CTA tile 128x128, BK=64,
// 3-stage cp.async pipeline, 128B-row XOR swizzle.
// ---------------------------------------------------------------------------
#define SMAT   16384u
#define SSTAGE 32768u
#define SWZ(row, ch) ((uint32_t)(row) * 128u + (((uint32_t)((ch) ^ ((row) & 7)) & 7u) << 4))

__global__ void __launch_bounds__(256, 2)
gemm_pipe(const __half* __restrict__ Xh, const __half* __restrict__ Wh_all,
          const float* __restrict__ b0, const float* __restrict__ b1,
          const float* __restrict__ b2,
          __half* __restrict__ Y0, __half* __restrict__ Y1, __half* __restrict__ Y2)
{
    const int z = blockIdx.z;
    const __half* Whi = Wh_all + (size_t)z * 65536;
    const float* bias = (z == 0) ? b0 : (z == 1) ? b1 : b2;
    __half*      Y    = (z == 0) ? Y0 : (z == 1) ? Y1 : Y2;

    extern __shared__ __align__(16) char smraw[];
    const uint32_t sb = smem_u32(smraw);

    const int tid  = threadIdx.x;
    const int lane = tid & 31;
    const int wid  = tid >> 5;
    const int wm   = wid & 3;
    const int wn   = wid >> 2;
    const int m0   = blockIdx.x * 128;
    const int n0   = blockIdx.y * 128;

    float acc[2][8][4];
#pragma unroll
    for (int i = 0; i < 2; i++)
#pragma unroll
        for (int j = 0; j < 8; j++)
#pragma unroll
            for (int t = 0; t < 4; t++) acc[i][j][t] = 0.f;

#define ISSUE(stage, kk)                                                          \
    do {                                                                          \
        const uint32_t s = sb + (stage) * SSTAGE;                                 \
        _Pragma("unroll")                                                         \
        for (int i = 0; i < 4; i++) {                                             \
            const int idx = tid + 256 * i;                                        \
            const int row = idx >> 3, ch = idx & 7;                               \
            const uint32_t d = SWZ(row, ch);                                      \
            cpa16(s + 0*SMAT + d, Xh  + (size_t)(m0 + row) * 256 + (kk) + ch * 8);\
            cpa16(s + 1*SMAT + d, Whi + (size_t)(n0 + row) * 256 + (kk) + ch * 8);\
        }                                                                         \
        asm volatile("cp.async.commit_group;" ::: "memory");                      \
    } while (0)

    const int l15 = lane & 15, lhi = lane >> 4;
    uint32_t arowb[2], axor[2], browb[4], bxor[4];
#pragma unroll
    for (int i = 0; i < 2; i++) {
        uint32_t r = (uint32_t)(wm * 32 + i * 16 + l15);
        arowb[i] = r * 128u;
        axor[i] = r & 7u;
    }
#pragma unroll
    for (int bp = 0; bp < 4; bp++) {
        uint32_t r = (uint32_t)(wn * 64 + bp * 16 + l15);
        browb[bp] = r * 128u;
        bxor[bp] = r & 7u;
    }

    ISSUE(0, 0);
    ISSUE(1, 64);

#pragma unroll 1
    for (int c = 0; c < 4; c++) {
        if (c < 3)
            asm volatile("cp.async.wait_group 1;" ::: "memory");
        else
            asm volatile("cp.async.wait_group 0;" ::: "memory");
        __syncthreads();
        if (c + 2 < 4) ISSUE((c + 2) % 3, (c + 2) * 64);

        const uint32_t st = sb + (uint32_t)(c % 3) * SSTAGE;
#pragma unroll
        for (int ks = 0; ks < 4; ks++) {
            const uint32_t cb = (uint32_t)(ks * 2 + lhi);
            uint32_t ah[2][4], b[8][2], r[4];

#pragma unroll
            for (int i = 0; i < 2; i++)
                ldm_x4(ah[i], st + 0*SMAT + arowb[i] + (((cb ^ axor[i]) & 7u) << 4));
#pragma unroll
            for (int bp = 0; bp < 4; bp++) {
                ldm_x4(r, st + 1*SMAT + browb[bp] + (((cb ^ bxor[bp]) & 7u) << 4));
                b[2*bp][0] = r[0]; b[2*bp+1][0] = r[1];
                b[2*bp][1] = r[2]; b[2*bp+1][1] = r[3];
            }
#pragma unroll
            for (int am = 0; am < 2; am++)
#pragma unroll
                for (int bn = 0; bn < 8; bn++) mma16816h(acc[am][bn], ah[am], b[bn]);
        }
    }

    // fp16 epilogue
    const int orow  = m0 + wm * 32 + (lane >> 2);
    const int ocol0 = n0 + wn * 64 + (lane & 3) * 2;
#pragma unroll
    for (int am = 0; am < 2; am++) {
#pragma unroll
        for (int bn = 0; bn < 8; bn++) {
            const int col = ocol0 + bn * 8;
            float2 bv = *(const float2*)(bias + col);
            uint32_t p0 = cvt2h(acc[am][bn][0] + bv.x, acc[am][bn][1] + bv.y);
            uint32_t p1 = cvt2h(acc[am][bn][2] + bv.x, acc[am][bn][3] + bv.y);
            *(uint32_t*)(Y + (size_t)(orow + am * 16)     * 256 + col) = p0;
            *(uint32_t*)(Y + (size_t)(orow + am * 16 + 8) * 256 + col) = p1;
        }
    }
}

// ---------------------------------------------------------------------------
// Fused attention: q/k/v fp16 inputs, fp32 math. blockIdx.x < B -> ads, else cat.
// ---------------------------------------------------------------------------
__device__ __forceinline__ float dot8(float4 a0, float4 b0, float4 a1, float4 b1) {
    return a0.x*b0.x + a0.y*b0.y + a0.z*b0.z + a0.w*b0.w
         + a1.x*b1.x + a1.y*b1.y + a1.z*b1.z + a1.w*b1.w;
}

__device__ void ads_part(float* sm, int b,
                         const __half* __restrict__ q, const __half* __restrict__ k,
                         const __half* __restrict__ v, const float* __restrict__ h,
                         float* __restrict__ out)
{
    float* Qs = sm;
    float* Ps = sm + 16 * 260;
    const int tid = threadIdx.x;
    const float scale = 0.0625f;

    // load Q (16 x 256 halves) -> fp32 smem
    {
        const uint2* src = (const uint2*)(q + (size_t)b * (NA * D));
#pragma unroll
        for (int h2 = 0; h2 < 4; h2++) {
            int i = tid + h2 * 256;
            int row = i >> 6, col = (i & 63) << 2;
            float4 vv = h4f(src[i]);
            float* d = Qs + row * 260 + col;
            d[0] = vv.x; d[1] = vv.y; d[2] = vv.z; d[3] = vv.w;
        }
    }
    __syncthreads();

    const int w = tid >> 5, l = tid & 31;

#pragma unroll 1
    for (int bat = 0; bat < 8; bat++) {
        const int c0 = w * 32 + bat * 4;
        float4 kA[4], kB[4];
#pragma unroll
        for (int kk = 0; kk < 4; kk++) {
            const __half* kr = k + ((size_t)b * NC + c0 + kk) * D;
            kA[kk] = h4f(((const uint2*)kr)[l]);
            kB[kk] = h4f(((const uint2*)(kr + 128))[l]);
        }
        float s[64];
#pragma unroll
        for (int i = 0; i < 64; i++) s[i] = 0.f;
#pragma unroll
        for (int j = 0; j < 16; j++) {
            float4 qA = *(const float4*)(Qs + j * 260 + 4 * l);
            float4 qB = *(const float4*)(Qs + j * 260 + 128 + 4 * l);
#pragma unroll
            for (int kk = 0; kk < 4; kk++)
                s[kk * 16 + j] += dot8(qA, kA[kk], qB, kB[kk]);
        }
#pragma unroll
        for (int off = 16; off > 0; off >>= 1)
#pragma unroll
            for (int i = 0; i < 64; i++)
                s[i] += __shfl_xor_sync(0xffffffffu, s[i], off);
        if (l < 16) {
#pragma unroll
            for (int kk = 0; kk < 4; kk++)
                Ps[l * 260 + c0 + kk] = s[kk * 16 + l] * scale;
        }
    }
    __syncthreads();

    {
        for (int r = w; r < 16; r += 8) {
            float* row = Ps + r * 260;
            float vals[8];
            float mx = -1e30f;
#pragma unroll
            for (int j = 0; j < 8; j++) { vals[j] = row[l + 32*j]; mx = fmaxf(mx, vals[j]); }
#pragma unroll
            for (int o = 16; o > 0; o >>= 1) mx = fmaxf(mx, __shfl_xor_sync(0xffffffffu, mx, o));
            float sum = 0.f;
#pragma unroll
            for (int j = 0; j < 8; j++) { vals[j] = __expf(vals[j] - mx); sum += vals[j]; }
#pragma unroll
            for (int o = 16; o > 0; o >>= 1) sum += __shfl_xor_sync(0xffffffffu, sum, o);
            float inv = 1.f / sum;
#pragma unroll
            for (int j = 0; j < 8; j++) row[l + 32*j] = vals[j] * inv;
        }
    }
    __syncthreads();

    const int aq = tid >> 6;
    const int dg = tid & 63;
    float4 u[4];
#pragma unroll
    for (int qi = 0; qi < 4; qi++) u[qi] = make_float4(0,0,0,0);
    const __half* vbase = v + (size_t)b * NC * D + dg * 4;
    const float* prow0 = Ps + (aq * 4) * 260;
#pragma unroll 4
    for (int c = 0; c < 256; c++) {
        float4 vv = h4f(*(const uint2*)(vbase + (size_t)c * D));
#pragma unroll
        for (int qi = 0; qi < 4; qi++) {
            float p = prow0[qi * 260 + c];
            u[qi].x += p * vv.x; u[qi].y += p * vv.y;
            u[qi].z += p * vv.z; u[qi].w += p * vv.w;
        }
    }

    float ssq[4];
#pragma unroll
    for (int qi = 0; qi < 4; qi++) {
        const float4 hv = *(const float4*)(h + ((size_t)b * NA + aq * 4 + qi) * D + dg * 4);
        u[qi].x += hv.x; u[qi].y += hv.y; u[qi].z += hv.z; u[qi].w += hv.w;
        ssq[qi] = u[qi].x*u[qi].x + u[qi].y*u[qi].y + u[qi].z*u[qi].z + u[qi].w*u[qi].w;
    }
#pragma unroll
    for (int off = 16; off > 0; off >>= 1)
#pragma unroll
        for (int qi = 0; qi < 4; qi++)
            ssq[qi] += __shfl_xor_sync(0xffffffffu, ssq[qi], off);
    if (l == 0) {
#pragma unroll
        for (int qi = 0; qi < 4; qi++) Qs[w * 4 + qi] = ssq[qi];
    }
    __syncthreads();
#pragma unroll
    for (int qi = 0; qi < 4; qi++) {
        float tot = Qs[(2 * aq) * 4 + qi] + Qs[(2 * aq + 1) * 4 + qi];
        float inv = 1.f / fmaxf(sqrtf(tot), 1e-12f);
        float4 o;
        o.x = u[qi].x * inv; o.y = u[qi].y * inv;
        o.z = u[qi].z * inv; o.w = u[qi].w * inv;
        *(float4*)(out + ((size_t)b * NA + aq * 4 + qi) * D + dg * 4) = o;
    }
}

__device__ void cat_part(float* sm, int idx,
                         const __half* __restrict__ q, const __half* __restrict__ k,
                         const __half* __restrict__ v, const float* __restrict__ h,
                         float* __restrict__ out)
{
    float* Ks = sm;
    float* Vs = sm + 16 * 260;
    const int tid = threadIdx.x;
    const int b = idx >> 3, xp = idx & 7;
    const float scale = 0.0625f;

    {
        const uint2* ks = (const uint2*)(k + (size_t)b * (NA * D));
        const uint2* vs = (const uint2*)(v + (size_t)b * (NA * D));
#pragma unroll
        for (int h2 = 0; h2 < 4; h2++) {
            int i = tid + h2 * 256;
            int row = i >> 6, col = (i & 63) << 2;
            float4 kv = h4f(ks[i]);
            float* dk = Ks + row * 260 + col;
            dk[0] = kv.x; dk[1] = kv.y; dk[2] = kv.z; dk[3] = kv.w;
            float4 vv = h4f(vs[i]);
            float* dv = Vs + row * 260 + col;
            dv[0] = vv.x; dv[1] = vv.y; dv[2] = vv.z; dv[3] = vv.w;
        }
    }
    __syncthreads();

    const int w = tid >> 5, l = tid & 31;
    const int c0 = xp * 32 + w * 4;
    const size_t gr0 = (size_t)b * NC + c0;

    float4 qA[4], qB[4];
#pragma unroll
    for (int qi = 0; qi < 4; qi++) {
        const __half* qr = q + (gr0 + qi) * D;
        qA[qi] = h4f(((const uint2*)qr)[l]);
        qB[qi] = h4f(((const uint2*)(qr + 128))[l]);
    }

    float s[64];
#pragma unroll
    for (int i = 0; i < 64; i++) s[i] = 0.f;
#pragma unroll
    for (int j = 0; j < 16; j++) {
        float4 kA = *(const float4*)(Ks + j * 260 + 4 * l);
        float4 kB = *(const float4*)(Ks + j * 260 + 128 + 4 * l);
#pragma unroll
        for (int qi = 0; qi < 4; qi++)
            s[qi * 16 + j] += dot8(qA[qi], kA, qB[qi], kB);
    }
#pragma unroll
    for (int off = 16; off > 0; off >>= 1)
#pragma unroll
        for (int i = 0; i < 64; i++)
            s[i] += __shfl_xor_sync(0xffffffffu, s[i], off);

#pragma unroll
    for (int qi = 0; qi < 4; qi++) {
        float mx = -1e30f;
#pragma unroll
        for (int j = 0; j < 16; j++) mx = fmaxf(mx, s[qi * 16 + j]);
        float sum = 0.f;
#pragma unroll
        for (int j = 0; j < 16; j++) {
            float e = __expf((s[qi * 16 + j] - mx) * scale);
            s[qi * 16 + j] = e; sum += e;
        }
        float inv = 1.f / sum;
#pragma unroll
        for (int j = 0; j < 16; j++) s[qi * 16 + j] *= inv;
    }

    float4 uA[4], uB[4];
#pragma unroll
    for (int qi = 0; qi < 4; qi++) { uA[qi] = make_float4(0,0,0,0); uB[qi] = uA[qi]; }
#pragma unroll
    for (int j = 0; j < 16; j++) {
        float4 vA = *(const float4*)(Vs + j * 260 + 4 * l);
        float4 vB = *(const float4*)(Vs + j * 260 + 128 + 4 * l);
#pragma unroll
        for (int qi = 0; qi < 4; qi++) {
            float p = s[qi * 16 + j];
            uA[qi].x += p * vA.x; uA[qi].y += p * vA.y;
            uA[qi].z += p * vA.z; uA[qi].w += p * vA.w;
            uB[qi].x += p * vB.x; uB[qi].y += p * vB.y;
            uB[qi].z += p * vB.z; uB[qi].w += p * vB.w;
        }
    }

#pragma unroll
    for (int qi = 0; qi < 4; qi++) {
        const float* hr = h + (gr0 + qi) * D;
        float4 rA = *(const float4*)(hr + 4 * l);
        float4 rB = *(const float4*)(hr + 128 + 4 * l);
        rA.x += uA[qi].x; rA.y += uA[qi].y; rA.z += uA[qi].z; rA.w += uA[qi].w;
        rB.x += uB[qi].x; rB.y += uB[qi].y; rB.z += uB[qi].z; rB.w += uB[qi].w;
        float nn = rA.x*rA.x + rA.y*rA.y + rA.z*rA.z + rA.w*rA.w
                 + rB.x*rB.x + rB.y*rB.y + rB.z*rB.z + rB.w*rB.w;
#pragma unroll
        for (int o = 16; o > 0; o >>= 1) nn += __shfl_xor_sync(0xffffffffu, nn, o);
        float inv = 1.f / fmaxf(sqrtf(nn), 1e-12f);
        float* orow = out + (gr0 + qi) * D;
        *(float4*)(orow + 4 * l) =
            make_float4(rA.x*inv, rA.y*inv, rA.z*inv, rA.w*inv);
        *(float4*)(orow + 128 + 4 * l) =
            make_float4(rB.x*inv, rB.y*inv, rB.z*inv, rB.w*inv);
    }
}

__global__ void __launch_bounds__(256)
attn_fused(const __half* qa, const __half* kc, const __half* vc, const float* hA,
           const __half* qc, const __half* ka, const __half* va, const float* hC,
           float* outA, float* outC, int B)
{
    extern __shared__ __align__(16) float sm[];
    if ((int)blockIdx.x < B)
        ads_part(sm, blockIdx.x, qa, kc, vc, hA, outA);
    else
        cat_part(sm, blockIdx.x - B, qc, ka, va, hC, outC);
}

// ---------------------------------------------------------------------------
// Launch
// ---------------------------------------------------------------------------
extern "C" void kernel_launch(void* const* d_in, const int* in_sizes, int n_in,
                              void* d_out, int out_size)
{
    const float* h_ads = (const float*)d_in[0];
    const float* h_cat = (const float*)d_in[1];
    const float* Wq_a = (const float*)d_in[2];  const float* bq_a = (const float*)d_in[3];
    const float* Wk_a = (const float*)d_in[4];  const float* bk_a = (const float*)d_in[5];
    const float* Wv_a = (const float*)d_in[6];  const float* bv_a = (const float*)d_in[7];
    const float* Wq_c = (const float*)d_in[8];  const float* bq_c = (const float*)d_in[9];
    const float* Wk_c = (const float*)d_in[10]; const float* bk_c = (const float*)d_in[11];
    const float* Wv_c = (const float*)d_in[12]; const float* bv_c = (const float*)d_in[13];

    const int M_ads = in_sizes[0] / D;   // 8192
    const int M_cat = in_sizes[1] / D;   // 131072
    const int B     = M_ads / NA;        // 512

    __half *qa, *ka, *va, *qc, *kc, *vc, *xah, *xch, *wh;
    cudaGetSymbolAddress((void**)&qa, g_qads);
    cudaGetSymbolAddress((void**)&ka, g_kads);
    cudaGetSymbolAddress((void**)&va, g_vads);
    cudaGetSymbolAddress((void**)&qc, g_qcat);
    cudaGetSymbolAddress((void**)&kc, g_kcat);
    cudaGetSymbolAddress((void**)&vc, g_vcat);
    cudaGetSymbolAddress((void**)&xah, gx_ads);
    cudaGetSymbolAddress((void**)&xch, gx_cat);
    cudaGetSymbolAddress((void**)&wh, gw_hi);

    // conversion prepass
    conv_x<<<512,  256>>>((const float4*)h_ads, (uint2*)xah, M_ads * D / 4);
    conv_x<<<4096, 256>>>((const float4*)h_cat, (uint2*)xch, M_cat * D / 4);
    conv_w<<<dim3(64, 6), 256>>>(Wq_a, Wk_a, Wv_a, Wq_c, Wk_c, Wv_c, (uint2*)wh);

    const int gemm_smem = 3 * SSTAGE;   // 98,304 B
    cudaFuncSetAttribute((const void*)gemm_pipe,
                         cudaFuncAttributeMaxDynamicSharedMemorySize, gemm_smem);

    gemm_pipe<<<dim3(M_ads / 128, 2, 3), 256, gemm_smem>>>(
        xah, wh, bq_a, bk_a, bv_a, qa, ka, va);
    gemm_pipe<<<dim3(M_cat / 128, 2, 3), 256, gemm_smem>>>(
        xch, wh + 3u * 65536u, bq_c, bk_c, bv_c, qc, kc, vc);

    const int attn_smem = 2 * 16 * 260 * 4;
    cudaFuncSetAttribute((const void*)attn_fused,
                         cudaFuncAttributeMaxDynamicSharedMemorySize, attn_smem);

    attn_fused<<<B + 8 * B, 256, attn_smem>>>(
        qa, kc, vc, h_ads, qc, ka, va, h_cat,
        (float*)d_out, (float*)d_out + (size_t)M_ads * D, B);
}

// round 11
// speedup vs baseline: 1.7398x; 1.2030x over previous
#include <cuda_runtime.h>
#include <cuda_fp16.h>
#include <math.h>
#include <stdint.h>

#define D   256
#define NA  16
#define NC  256

// ---------------------------------------------------------------------------
// Scratch (device globals — no allocation allowed in kernel_launch)
// ---------------------------------------------------------------------------
__device__ __half g_qads[8192u  * 256u];
__device__ __half g_kads[8192u  * 256u];
__device__ __half g_vads[8192u  * 256u];
__device__ __half g_qcat[131072u * 256u];
__device__ __half g_kcat[131072u * 256u];
__device__ __half g_vcat[131072u * 256u];
__device__ __half gx_ads[8192u  * 256u];
__device__ __half gx_cat[131072u * 256u];
__device__ __half gw_hi[6u * 65536u];

// ---------------------------------------------------------------------------
// PTX helpers (arch-neutral sm_80+ — harness ptxas target is plain sm_103)
// ---------------------------------------------------------------------------
__device__ __forceinline__ uint32_t smem_u32(const void* p) {
    uint32_t a;
    asm("{ .reg .u64 t; cvta.to.shared.u64 t, %1; cvt.u32.u64 %0, t; }"
        : "=r"(a) : "l"(p));
    return a;
}
__device__ __forceinline__ void cpa16(uint32_t dst, const void* src) {
    asm volatile("cp.async.ca.shared.global [%0], [%1], 16;"
                 :: "r"(dst), "l"(src) : "memory");
}
__device__ __forceinline__ void ldm_x4(uint32_t* r, uint32_t addr) {
    asm volatile("ldmatrix.sync.aligned.m8n8.x4.shared.b16 {%0,%1,%2,%3}, [%4];"
                 : "=r"(r[0]), "=r"(r[1]), "=r"(r[2]), "=r"(r[3]) : "r"(addr));
}
__device__ __forceinline__ void mma16816h(float* c, const uint32_t* a,
                                          const uint32_t* b) {
    asm volatile(
        "mma.sync.aligned.m16n8k16.row.col.f32.f16.f16.f32 "
        "{%0,%1,%2,%3}, {%4,%5,%6,%7}, {%8,%9}, {%0,%1,%2,%3};"
        : "+f"(c[0]), "+f"(c[1]), "+f"(c[2]), "+f"(c[3])
        : "r"(a[0]), "r"(a[1]), "r"(a[2]), "r"(a[3]), "r"(b[0]), "r"(b[1]));
}
// pack (a -> low, b -> high)
__device__ __forceinline__ uint32_t cvt2h(float a, float b) {
    uint32_t hp;
    asm("cvt.rn.f16x2.f32 %0, %1, %2;" : "=r"(hp) : "f"(b), "f"(a));
    return hp;
}
// unpack 4 halves -> float4
__device__ __forceinline__ float4 h4f(uint2 v) {
    __half2 h0 = *reinterpret_cast<__half2*>(&v.x);
    __half2 h1 = *reinterpret_cast<__half2*>(&v.y);
    float2 f0 = __half22float2(h0), f1 = __half22float2(h1);
    return make_float4(f0.x, f0.y, f1.x, f1.y);
}
__device__ __forceinline__ float dot4(float4 a, float4 b) {
    return a.x*b.x + a.y*b.y + a.z*b.z + a.w*b.w;
}

// ---------------------------------------------------------------------------
// Conversion prepass: fp32 -> packed fp16
// ---------------------------------------------------------------------------
__global__ void __launch_bounds__(256)
conv_x(const float4* __restrict__ src, uint2* __restrict__ hi, int n4)
{
    for (int i = blockIdx.x * blockDim.x + threadIdx.x; i < n4;
         i += gridDim.x * blockDim.x) {
        float4 f = src[i];
        hi[i] = make_uint2(cvt2h(f.x, f.y), cvt2h(f.z, f.w));
    }
}

__global__ void __launch_bounds__(256)
conv_w(const float* w0, const float* w1, const float* w2,
       const float* w3, const float* w4, const float* w5,
       uint2* __restrict__ hi)
{
    const int z = blockIdx.y;
    const float* W = (z == 0) ? w0 : (z == 1) ? w1 : (z == 2) ? w2
                   : (z == 3) ? w3 : (z == 4) ? w4 : w5;
    const int i = blockIdx.x * 256 + threadIdx.x;
    float4 f = ((const float4*)W)[i];
    hi[z * 16384 + i] = make_uint2(cvt2h(f.x, f.y), cvt2h(f.z, f.w));
}

// ---------------------------------------------------------------------------
// Pipelined fp16 GEMM (unchanged from R10)
// ---------------------------------------------------------------------------
#define SMAT   16384u
#define SSTAGE 32768u
#define SWZ(row, ch) ((uint32_t)(row) * 128u + (((uint32_t)((ch) ^ ((row) & 7)) & 7u) << 4))

__global__ void __launch_bounds__(256, 2)
gemm_pipe(const __half* __restrict__ Xh, const __half* __restrict__ Wh_all,
          const float* __restrict__ b0, const float* __restrict__ b1,
          const float* __restrict__ b2,
          __half* __restrict__ Y0, __half* __restrict__ Y1, __half* __restrict__ Y2)
{
    const int z = blockIdx.z;
    const __half* Whi = Wh_all + (size_t)z * 65536;
    const float* bias = (z == 0) ? b0 : (z == 1) ? b1 : b2;
    __half*      Y    = (z == 0) ? Y0 : (z == 1) ? Y1 : Y2;

    extern __shared__ __align__(16) char smraw[];
    const uint32_t sb = smem_u32(smraw);

    const int tid  = threadIdx.x;
    const int lane = tid & 31;
    const int wid  = tid >> 5;
    const int wm   = wid & 3;
    const int wn   = wid >> 2;
    const int m0   = blockIdx.x * 128;
    const int n0   = blockIdx.y * 128;

    float acc[2][8][4];
#pragma unroll
    for (int i = 0; i < 2; i++)
#pragma unroll
        for (int j = 0; j < 8; j++)
#pragma unroll
            for (int t = 0; t < 4; t++) acc[i][j][t] = 0.f;

#define ISSUE(stage, kk)                                                          \
    do {                                                                          \
        const uint32_t s = sb + (stage) * SSTAGE;                                 \
        _Pragma("unroll")                                                         \
        for (int i = 0; i < 4; i++) {                                             \
            const int idx = tid + 256 * i;                                        \
            const int row = idx >> 3, ch = idx & 7;                               \
            const uint32_t d = SWZ(row, ch);                                      \
            cpa16(s + 0*SMAT + d, Xh  + (size_t)(m0 + row) * 256 + (kk) + ch * 8);\
            cpa16(s + 1*SMAT + d, Whi + (size_t)(n0 + row) * 256 + (kk) + ch * 8);\
        }                                                                         \
        asm volatile("cp.async.commit_group;" ::: "memory");                      \
    } while (0)

    const int l15 = lane & 15, lhi = lane >> 4;
    uint32_t arowb[2], axor[2], browb[4], bxor[4];
#pragma unroll
    for (int i = 0; i < 2; i++) {
        uint32_t r = (uint32_t)(wm * 32 + i * 16 + l15);
        arowb[i] = r * 128u;
        axor[i] = r & 7u;
    }
#pragma unroll
    for (int bp = 0; bp < 4; bp++) {
        uint32_t r = (uint32_t)(wn * 64 + bp * 16 + l15);
        browb[bp] = r * 128u;
        bxor[bp] = r & 7u;
    }

    ISSUE(0, 0);
    ISSUE(1, 64);

#pragma unroll 1
    for (int c = 0; c < 4; c++) {
        if (c < 3)
            asm volatile("cp.async.wait_group 1;" ::: "memory");
        else
            asm volatile("cp.async.wait_group 0;" ::: "memory");
        __syncthreads();
        if (c + 2 < 4) ISSUE((c + 2) % 3, (c + 2) * 64);

        const uint32_t st = sb + (uint32_t)(c % 3) * SSTAGE;
#pragma unroll
        for (int ks = 0; ks < 4; ks++) {
            const uint32_t cb = (uint32_t)(ks * 2 + lhi);
            uint32_t ah[2][4], b[8][2], r[4];

#pragma unroll
            for (int i = 0; i < 2; i++)
                ldm_x4(ah[i], st + 0*SMAT + arowb[i] + (((cb ^ axor[i]) & 7u) << 4));
#pragma unroll
            for (int bp = 0; bp < 4; bp++) {
                ldm_x4(r, st + 1*SMAT + browb[bp] + (((cb ^ bxor[bp]) & 7u) << 4));
                b[2*bp][0] = r[0]; b[2*bp+1][0] = r[1];
                b[2*bp][1] = r[2]; b[2*bp+1][1] = r[3];
            }
#pragma unroll
            for (int am = 0; am < 2; am++)
#pragma unroll
                for (int bn = 0; bn < 8; bn++) mma16816h(acc[am][bn], ah[am], b[bn]);
        }
    }

    const int orow  = m0 + wm * 32 + (lane >> 2);
    const int ocol0 = n0 + wn * 64 + (lane & 3) * 2;
#pragma unroll
    for (int am = 0; am < 2; am++) {
#pragma unroll
        for (int bn = 0; bn < 8; bn++) {
            const int col = ocol0 + bn * 8;
            float2 bv = *(const float2*)(bias + col);
            uint32_t p0 = cvt2h(acc[am][bn][0] + bv.x, acc[am][bn][1] + bv.y);
            uint32_t p1 = cvt2h(acc[am][bn][2] + bv.x, acc[am][bn][3] + bv.y);
            *(uint32_t*)(Y + (size_t)(orow + am * 16)     * 256 + col) = p0;
            *(uint32_t*)(Y + (size_t)(orow + am * 16 + 8) * 256 + col) = p1;
        }
    }
}

// ---------------------------------------------------------------------------
// Fused attention v2: 8-lane d-split score phases (reduce = 3 xor stages).
// ---------------------------------------------------------------------------
__device__ void ads_part(float* sm, int b,
                         const __half* __restrict__ q, const __half* __restrict__ k,
                         const __half* __restrict__ v, const float* __restrict__ h,
                         float* __restrict__ out)
{
    float* Qs = sm;             // 16 x 260 fp32
    float* Ps = sm + 16 * 260;  // 16 x 260
    const int tid = threadIdx.x;
    const float scale = 0.0625f;

    // load Q (16 x 256 halves) -> fp32 smem
    {
        const uint2* src = (const uint2*)(q + (size_t)b * (NA * D));
#pragma unroll
        for (int h2 = 0; h2 < 4; h2++) {
            int i = tid + h2 * 256;
            int row = i >> 6, col = (i & 63) << 2;
            float4 vv = h4f(src[i]);
            float* d = Qs + row * 260 + col;
            d[0] = vv.x; d[1] = vv.y; d[2] = vv.z; d[3] = vv.w;
        }
    }
    __syncthreads();

    const int w = tid >> 5, l = tid & 31;
    const int g = l >> 3, t = l & 7;

    // scores: 2 super-batches; group g owns 4 keys, lane t owns dims 32c+4t
#pragma unroll 1
    for (int sb2 = 0; sb2 < 2; sb2++) {
        const int kbase = w * 32 + sb2 * 16 + g * 4;
        float s[16][4];
#pragma unroll
        for (int qi = 0; qi < 16; qi++)
#pragma unroll
            for (int kk = 0; kk < 4; kk++) s[qi][kk] = 0.f;

#pragma unroll
        for (int c = 0; c < 8; c++) {
            const int d0 = 32 * c + 4 * t;
            float4 kf[4];
#pragma unroll
            for (int kk = 0; kk < 4; kk++)
                kf[kk] = h4f(*(const uint2*)(k + ((size_t)b * NC + kbase + kk) * D + d0));
#pragma unroll
            for (int qi = 0; qi < 16; qi++) {
                float4 qf = *(const float4*)(Qs + qi * 260 + d0);
#pragma unroll
                for (int kk = 0; kk < 4; kk++)
                    s[qi][kk] += dot4(qf, kf[kk]);
            }
        }
        // reduce over 8 dim-lanes
#pragma unroll
        for (int off = 1; off < 8; off <<= 1)
#pragma unroll
            for (int qi = 0; qi < 16; qi++)
#pragma unroll
                for (int kk = 0; kk < 4; kk++)
                    s[qi][kk] += __shfl_xor_sync(0xffffffffu, s[qi][kk], off);
        if (t == 0) {
#pragma unroll
            for (int qi = 0; qi < 16; qi++)
#pragma unroll
                for (int kk = 0; kk < 4; kk++)
                    Ps[qi * 260 + kbase + kk] = s[qi][kk] * scale;
        }
    }
    __syncthreads();

    // softmax over 256 keys, warp per row (unchanged)
    {
        for (int r = w; r < 16; r += 8) {
            float* row = Ps + r * 260;
            float vals[8];
            float mx = -1e30f;
#pragma unroll
            for (int j = 0; j < 8; j++) { vals[j] = row[l + 32*j]; mx = fmaxf(mx, vals[j]); }
#pragma unroll
            for (int o = 16; o > 0; o >>= 1) mx = fmaxf(mx, __shfl_xor_sync(0xffffffffu, mx, o));
            float sum = 0.f;
#pragma unroll
            for (int j = 0; j < 8; j++) { vals[j] = __expf(vals[j] - mx); sum += vals[j]; }
#pragma unroll
            for (int o = 16; o > 0; o >>= 1) sum += __shfl_xor_sync(0xffffffffu, sum, o);
            float inv = 1.f / sum;
#pragma unroll
            for (int j = 0; j < 8; j++) row[l + 32*j] = vals[j] * inv;
        }
    }
    __syncthreads();

    // U = P @ V (unchanged)
    const int aq = tid >> 6;
    const int dg = tid & 63;
    float4 u[4];
#pragma unroll
    for (int qi = 0; qi < 4; qi++) u[qi] = make_float4(0,0,0,0);
    const __half* vbase = v + (size_t)b * NC * D + dg * 4;
    const float* prow0 = Ps + (aq * 4) * 260;
#pragma unroll 4
    for (int c = 0; c < 256; c++) {
        float4 vv = h4f(*(const uint2*)(vbase + (size_t)c * D));
#pragma unroll
        for (int qi = 0; qi < 4; qi++) {
            float p = prow0[qi * 260 + c];
            u[qi].x += p * vv.x; u[qi].y += p * vv.y;
            u[qi].z += p * vv.z; u[qi].w += p * vv.w;
        }
    }

    float ssq[4];
#pragma unroll
    for (int qi = 0; qi < 4; qi++) {
        const float4 hv = *(const float4*)(h + ((size_t)b * NA + aq * 4 + qi) * D + dg * 4);
        u[qi].x += hv.x; u[qi].y += hv.y; u[qi].z += hv.z; u[qi].w += hv.w;
        ssq[qi] = u[qi].x*u[qi].x + u[qi].y*u[qi].y + u[qi].z*u[qi].z + u[qi].w*u[qi].w;
    }
#pragma unroll
    for (int off = 16; off > 0; off >>= 1)
#pragma unroll
        for (int qi = 0; qi < 4; qi++)
            ssq[qi] += __shfl_xor_sync(0xffffffffu, ssq[qi], off);
    if (l == 0) {
#pragma unroll
        for (int qi = 0; qi < 4; qi++) Qs[w * 4 + qi] = ssq[qi];
    }
    __syncthreads();
#pragma unroll
    for (int qi = 0; qi < 4; qi++) {
        float tot = Qs[(2 * aq) * 4 + qi] + Qs[(2 * aq + 1) * 4 + qi];
        float inv = 1.f / fmaxf(sqrtf(tot), 1e-12f);
        float4 o;
        o.x = u[qi].x * inv; o.y = u[qi].y * inv;
        o.z = u[qi].z * inv; o.w = u[qi].w * inv;
        *(float4*)(out + ((size_t)b * NA + aq * 4 + qi) * D + dg * 4) = o;
    }
}

__device__ void cat_part(float* sm, int idx,
                         const __half* __restrict__ q, const __half* __restrict__ k,
                         const __half* __restrict__ v, const float* __restrict__ h,
                         float* __restrict__ out)
{
    float* Ks = sm;
    float* Vs = sm + 16 * 260;
    const int tid = threadIdx.x;
    const int b = idx >> 3, xp = idx & 7;
    const float scale = 0.0625f;

    {
        const uint2* ks = (const uint2*)(k + (size_t)b * (NA * D));
        const uint2* vs = (const uint2*)(v + (size_t)b * (NA * D));
#pragma unroll
        for (int h2 = 0; h2 < 4; h2++) {
            int i = tid + h2 * 256;
            int row = i >> 6, col = (i & 63) << 2;
            float4 kv = h4f(ks[i]);
            float* dk = Ks + row * 260 + col;
            dk[0] = kv.x; dk[1] = kv.y; dk[2] = kv.z; dk[3] = kv.w;
            float4 vv = h4f(vs[i]);
            float* dv = Vs + row * 260 + col;
            dv[0] = vv.x; dv[1] = vv.y; dv[2] = vv.z; dv[3] = vv.w;
        }
    }
    __syncthreads();

    const int w = tid >> 5, l = tid & 31;
    const int g = l >> 3, t = l & 7;
    const int c0 = xp * 32 + w * 4;
    const size_t gr0 = (size_t)b * NC + c0;

    // scores: group g owns keys 4g..4g+3, lane t owns dims 32c+4t
    float s[4][4];
#pragma unroll
    for (int qi = 0; qi < 4; qi++)
#pragma unroll
        for (int kk = 0; kk < 4; kk++) s[qi][kk] = 0.f;

#pragma unroll
    for (int c = 0; c < 8; c++) {
        const int d0 = 32 * c + 4 * t;
        float4 kf[4];
#pragma unroll
        for (int kk = 0; kk < 4; kk++)
            kf[kk] = *(const float4*)(Ks + (4 * g + kk) * 260 + d0);
#pragma unroll
        for (int qi = 0; qi < 4; qi++) {
            float4 qf = h4f(*(const uint2*)(q + (gr0 + qi) * D + d0));
#pragma unroll
            for (int kk = 0; kk < 4; kk++)
                s[qi][kk] += dot4(qf, kf[kk]);
        }
    }
    // reduce over 8 dim-lanes
#pragma unroll
    for (int off = 1; off < 8; off <<= 1)
#pragma unroll
        for (int qi = 0; qi < 4; qi++)
#pragma unroll
            for (int kk = 0; kk < 4; kk++)
                s[qi][kk] += __shfl_xor_sync(0xffffffffu, s[qi][kk], off);

    // softmax: group-local 4 keys + cross-group combine (keys 0..15)
    float p[4][4];
#pragma unroll
    for (int qi = 0; qi < 4; qi++) {
        float mx = fmaxf(fmaxf(s[qi][0], s[qi][1]), fmaxf(s[qi][2], s[qi][3]));
#pragma unroll
        for (int off = 8; off < 32; off <<= 1)
            mx = fmaxf(mx, __shfl_xor_sync(0xffffffffu, mx, off));
        float sum = 0.f;
#pragma unroll
        for (int kk = 0; kk < 4; kk++) {
            p[qi][kk] = __expf((s[qi][kk] - mx) * scale);
            sum += p[qi][kk];
        }
#pragma unroll
        for (int off = 8; off < 32; off <<= 1)
            sum += __shfl_xor_sync(0xffffffffu, sum, off);
        float inv = 1.f / sum;
#pragma unroll
        for (int kk = 0; kk < 4; kk++) p[qi][kk] *= inv;
    }

    // U = P @ V: lane covers dims 4l and 128+4l; p broadcast via shfl
    float4 uA[4], uB[4];
#pragma unroll
    for (int qi = 0; qi < 4; qi++) { uA[qi] = make_float4(0,0,0,0); uB[qi] = uA[qi]; }
#pragma unroll
    for (int j = 0; j < 16; j++) {
        const int src = (j >> 2) << 3;
        float pq[4];
#pragma unroll
        for (int qi = 0; qi < 4; qi++)
            pq[qi] = __shfl_sync(0xffffffffu, p[qi][j & 3], src);
        float4 vA = *(const float4*)(Vs + j * 260 + 4 * l);
        float4 vB = *(const float4*)(Vs + j * 260 + 128 + 4 * l);
#pragma unroll
        for (int qi = 0; qi < 4; qi++) {
            uA[qi].x += pq[qi] * vA.x; uA[qi].y += pq[qi] * vA.y;
            uA[qi].z += pq[qi] * vA.z; uA[qi].w += pq[qi] * vA.w;
            uB[qi].x += pq[qi] * vB.x; uB[qi].y += pq[qi] * vB.y;
            uB[qi].z += pq[qi] * vB.z; uB[qi].w += pq[qi] * vB.w;
        }
    }

#pragma unroll
    for (int qi = 0; qi < 4; qi++) {
        const float* hr = h + (gr0 + qi) * D;
        float4 rA = *(const float4*)(hr + 4 * l);
        float4 rB = *(const float4*)(hr + 128 + 4 * l);
        rA.x += uA[qi].x; rA.y += uA[qi].y; rA.z += uA[qi].z; rA.w += uA[qi].w;
        rB.x += uB[qi].x; rB.y += uB[qi].y; rB.z += uB[qi].z; rB.w += uB[qi].w;
        float nn = rA.x*rA.x + rA.y*rA.y + rA.z*rA.z + rA.w*rA.w
                 + rB.x*rB.x + rB.y*rB.y + rB.z*rB.z + rB.w*rB.w;
#pragma unroll
        for (int o = 16; o > 0; o >>= 1) nn += __shfl_xor_sync(0xffffffffu, nn, o);
        float inv = 1.f / fmaxf(sqrtf(nn), 1e-12f);
        float* orow = out + (gr0 + qi) * D;
        *(float4*)(orow + 4 * l) =
            make_float4(rA.x*inv, rA.y*inv, rA.z*inv, rA.w*inv);
        *(float4*)(orow + 128 + 4 * l) =
            make_float4(rB.x*inv, rB.y*inv, rB.z*inv, rB.w*inv);
    }
}

__global__ void __launch_bounds__(256)
attn_fused(const __half* qa, const __half* kc, const __half* vc, const float* hA,
           const __half* qc, const __half* ka, const __half* va, const float* hC,
           float* outA, float* outC, int B)
{
    extern __shared__ __align__(16) float sm[];
    if ((int)blockIdx.x < B)
        ads_part(sm, blockIdx.x, qa, kc, vc, hA, outA);
    else
        cat_part(sm, blockIdx.x - B, qc, ka, va, hC, outC);
}

// ---------------------------------------------------------------------------
// Launch
// ---------------------------------------------------------------------------
extern "C" void kernel_launch(void* const* d_in, const int* in_sizes, int n_in,
                              void* d_out, int out_size)
{
    const float* h_ads = (const float*)d_in[0];
    const float* h_cat = (const float*)d_in[1];
    const float* Wq_a = (const float*)d_in[2];  const float* bq_a = (const float*)d_in[3];
    const float* Wk_a = (const float*)d_in[4];  const float* bk_a = (const float*)d_in[5];
    const float* Wv_a = (const float*)d_in[6];  const float* bv_a = (const float*)d_in[7];
    const float* Wq_c = (const float*)d_in[8];  const float* bq_c = (const float*)d_in[9];
    const float* Wk_c = (const float*)d_in[10]; const float* bk_c = (const float*)d_in[11];
    const float* Wv_c = (const float*)d_in[12]; const float* bv_c = (const float*)d_in[13];

    const int M_ads = in_sizes[0] / D;   // 8192
    const int M_cat = in_sizes[1] / D;   // 131072
    const int B     = M_ads / NA;        // 512

    __half *qa, *ka, *va, *qc, *kc, *vc, *xah, *xch, *wh;
    cudaGetSymbolAddress((void**)&qa, g_qads);
    cudaGetSymbolAddress((void**)&ka, g_kads);
    cudaGetSymbolAddress((void**)&va, g_vads);
    cudaGetSymbolAddress((void**)&qc, g_qcat);
    cudaGetSymbolAddress((void**)&kc, g_kcat);
    cudaGetSymbolAddress((void**)&vc, g_vcat);
    cudaGetSymbolAddress((void**)&xah, gx_ads);
    cudaGetSymbolAddress((void**)&xch, gx_cat);
    cudaGetSymbolAddress((void**)&wh, gw_hi);

    // conversion prepass
    conv_x<<<512,  256>>>((const float4*)h_ads, (uint2*)xah, M_ads * D / 4);
    conv_x<<<4096, 256>>>((const float4*)h_cat, (uint2*)xch, M_cat * D / 4);
    conv_w<<<dim3(64, 6), 256>>>(Wq_a, Wk_a, Wv_a, Wq_c, Wk_c, Wv_c, (uint2*)wh);

    const int gemm_smem = 3 * SSTAGE;   // 98,304 B
    cudaFuncSetAttribute((const void*)gemm_pipe,
                         cudaFuncAttributeMaxDynamicSharedMemorySize, gemm_smem);

    gemm_pipe<<<dim3(M_ads / 128, 2, 3), 256, gemm_smem>>>(
        xah, wh, bq_a, bk_a, bv_a, qa, ka, va);
    gemm_pipe<<<dim3(M_cat / 128, 2, 3), 256, gemm_smem>>>(
        xch, wh + 3u * 65536u, bq_c, bk_c, bv_c, qc, kc, vc);

    const int attn_smem = 2 * 16 * 260 * 4;
    cudaFuncSetAttribute((const void*)attn_fused,
                         cudaFuncAttributeMaxDynamicSharedMemorySize, attn_smem);

    attn_fused<<<B + 8 * B, 256, attn_smem>>>(
        qa, kc, vc, h_ads, qc, ka, va, h_cat,
        (float*)d_out, (float*)d_out + (size_t)M_ads * D, B);
}